// round 7
// baseline (speedup 1.0000x reference)
#include <cuda_runtime.h>
#include <cuda_bf16.h>
#include <math.h>

// Problem constants
#define BB   32
#define TT   4096
#define DZC  128
#define NDC  32
#define DHC  128
#define GG   384            // 3*DZ
#define IND  192            // 2*ND + DH

#define TBLK      128                 // timesteps per GEMM tile
#define NTBLK     (TT / TBLK)         // 32 t-blocks per batch
#define GEMM_CTAS (NTBLK * BB * 3)    // 3072
#define SCAN_CTAS 16                  // 2 batches per scan CTA

// ---------------- scratch (no cudaMalloc allowed) ----------------
__device__ float        g_gi[(size_t)BB * TT * GG + 2 * GG];  // pad for tail prefetch
__device__ unsigned int g_cnt[BB * NTBLK];                    // tile counters

// ---------------- packed fp32x2 helpers (sm_100+) ----------------
__device__ __forceinline__ void fma2(unsigned long long& d,
                                     unsigned long long a,
                                     unsigned long long b) {
    asm("fma.rn.f32x2 %0, %1, %2, %0;" : "+l"(d) : "l"(a), "l"(b));
}
__device__ __forceinline__ unsigned long long dup2(float a) {
    unsigned long long r;
    asm("mov.b64 %0, {%1, %1};" : "=l"(r) : "f"(a));
    return r;
}
__device__ __forceinline__ void unpk(unsigned long long v, float& x, float& y) {
    asm("mov.b64 {%0, %1}, %2;" : "=f"(x), "=f"(y) : "l"(v));
}
__device__ __forceinline__ float ex2f_(float x) {
    float y; asm("ex2.approx.f32 %0, %1;" : "=f"(y) : "f"(x)); return y;
}
__device__ __forceinline__ float rcpf_(float x) {
    float y; asm("rcp.approx.f32 %0, %1;" : "=f"(y) : "f"(x)); return y;
}
__device__ __forceinline__ float sigmoidf_(float x) {
    float e = ex2f_(-1.4426950408889634f * x);
    return rcpf_(1.0f + e);
}
__device__ __forceinline__ float tanhf_(float x) {
    float xc = fminf(fmaxf(x, -20.0f), 20.0f);
    float e = ex2f_(-2.8853900817779268f * xc);   // exp(-2x)
    return (1.0f - e) * rcpf_(1.0f + e);
}
__device__ __forceinline__ unsigned int ldvol_(const unsigned int* p) {
    unsigned int v;
    asm volatile("ld.volatile.global.b32 %0, [%1];" : "=r"(v) : "l"(p));
    return v;
}

// =====================================================================
// Fused kernel. blockIdx.x < 16  -> scan role (2 batches per CTA)
//               blockIdx.x >= 16 -> GEMM tile role (t-block-major order)
// GEMM adds b_ih and, for r/u rows (g<256), also b_hh (bias folding).
// =====================================================================
#define Bb 128
#define BN 128
#define BK 16

struct ScanSmem {
    float dt0[TT + 4];
    float dt1[TT + 4];
    float zA0[DZC], zB0[DZC];
    float zA1[DZC], zB1[DZC];
};
struct GemmSmem {
    float As[2][BK][Bb];
    float Bs[2][BK][BN];
};

__global__ __launch_bounds__(256, 1) void fused_kernel(
    const float* __restrict__ z0, const float* __restrict__ t_dyn,
    const int* __restrict__ dyn_lens,
    const float* __restrict__ Y, const float* __restrict__ M,
    const float* __restrict__ H,
    const float* __restrict__ W_ih, const float* __restrict__ b_ih,
    const float* __restrict__ W_hh, const float* __restrict__ b_hh,
    const float* __restrict__ log_gamma,
    float* __restrict__ z_final, float* __restrict__ Z_traj)
{
    __shared__ __align__(16) union { ScanSmem scan; GemmSmem gemm; } sm;

    const int tid = threadIdx.x;

    if (blockIdx.x >= SCAN_CTAS) {
        // ================= GEMM role =================
        const int gidx = blockIdx.x - SCAN_CTAS;
        const int tb   = gidx / (BB * 3);
        const int rem  = gidx % (BB * 3);
        const int b    = rem / 3;
        const int gblk = rem % 3;
        const int bt0  = b * TT + tb * TBLK;
        const int g0   = gblk * BN;

        float* gi = g_gi;
        const int tx = tid & 15;
        const int ty = tid >> 4;

        unsigned long long acc[8][4];
        #pragma unroll
        for (int i = 0; i < 8; i++)
            #pragma unroll
            for (int j = 0; j < 4; j++) acc[i][j] = 0ull;

        auto loadA = [&](int stage, int kc) {
            #pragma unroll
            for (int i = 0; i < 2; i++) {
                int e  = tid + 256 * i;
                int m  = e & 127;
                int k4 = e >> 7;
                int kk = kc * BK + k4 * 4;
                int bt = bt0 + m;
                float4 v;
                if (kk < 32)       v = *(const float4*)(Y + (size_t)bt * NDC + kk);
                else if (kk < 64)  v = *(const float4*)(M + (size_t)bt * NDC + (kk - 32));
                else               v = *(const float4*)(H + (size_t)bt * DHC + (kk - 64));
                sm.gemm.As[stage][k4 * 4 + 0][m] = v.x;
                sm.gemm.As[stage][k4 * 4 + 1][m] = v.y;
                sm.gemm.As[stage][k4 * 4 + 2][m] = v.z;
                sm.gemm.As[stage][k4 * 4 + 3][m] = v.w;
            }
        };
        auto loadB = [&](int stage, int kc) {
            #pragma unroll
            for (int i = 0; i < 2; i++) {
                int e  = tid + 256 * i;
                int g  = e & 127;
                int k4 = e >> 7;
                int kk = kc * BK + k4 * 4;
                float4 v = *(const float4*)(W_ih + (size_t)(g0 + g) * IND + kk);
                sm.gemm.Bs[stage][k4 * 4 + 0][g] = v.x;
                sm.gemm.Bs[stage][k4 * 4 + 1][g] = v.y;
                sm.gemm.Bs[stage][k4 * 4 + 2][g] = v.z;
                sm.gemm.Bs[stage][k4 * 4 + 3][g] = v.w;
            }
        };

        loadA(0, 0); loadB(0, 0);
        __syncthreads();

        const int NKC = IND / BK;   // 12
        for (int kc = 0; kc < NKC; kc++) {
            int cur = kc & 1, nxt = cur ^ 1;
            if (kc + 1 < NKC) { loadA(nxt, kc + 1); loadB(nxt, kc + 1); }
            #pragma unroll
            for (int k = 0; k < BK; k++) {
                float a[8];
                *(float4*)&a[0] = *(const float4*)&sm.gemm.As[cur][k][ty * 8];
                *(float4*)&a[4] = *(const float4*)&sm.gemm.As[cur][k][ty * 8 + 4];
                unsigned long long bv[4];
                {
                    ulonglong2 b0 = *(const ulonglong2*)&sm.gemm.Bs[cur][k][tx * 8];
                    ulonglong2 b1 = *(const ulonglong2*)&sm.gemm.Bs[cur][k][tx * 8 + 4];
                    bv[0] = b0.x; bv[1] = b0.y; bv[2] = b1.x; bv[3] = b1.y;
                }
                #pragma unroll
                for (int i = 0; i < 8; i++) {
                    unsigned long long ad = dup2(a[i]);
                    fma2(acc[i][0], ad, bv[0]);
                    fma2(acc[i][1], ad, bv[1]);
                    fma2(acc[i][2], ad, bv[2]);
                    fma2(acc[i][3], ad, bv[3]);
                }
            }
            __syncthreads();
        }

        // bias: b_ih always; fold b_hh for r/u rows (g < 256)
        float bia[8];
        *(float4*)&bia[0] = *(const float4*)(b_ih + g0 + tx * 8);
        *(float4*)&bia[4] = *(const float4*)(b_ih + g0 + tx * 8 + 4);
        if (gblk < 2) {
            float bh[8];
            *(float4*)&bh[0] = *(const float4*)(b_hh + g0 + tx * 8);
            *(float4*)&bh[4] = *(const float4*)(b_hh + g0 + tx * 8 + 4);
            #pragma unroll
            for (int j = 0; j < 8; j++) bia[j] += bh[j];
        }

        #pragma unroll
        for (int i = 0; i < 8; i++) {
            float c[8];
            unpk(acc[i][0], c[0], c[1]);
            unpk(acc[i][1], c[2], c[3]);
            unpk(acc[i][2], c[4], c[5]);
            unpk(acc[i][3], c[6], c[7]);
            #pragma unroll
            for (int j = 0; j < 8; j++) c[j] += bia[j];
            int bt = bt0 + ty * 8 + i;
            float* outp = gi + (size_t)bt * GG + g0 + tx * 8;
            *(float4*)(outp)     = *(float4*)&c[0];
            *(float4*)(outp + 4) = *(float4*)&c[4];
        }

        __threadfence();
        __syncthreads();
        if (tid == 0) atomicAdd(&g_cnt[b * NTBLK + tb], 1u);
        return;
    }

    // ================= scan role: 2 batches per CTA =================
    const int b0 = 2 * blockIdx.x;
    const int b1 = b0 + 1;
    const int j  = tid >> 1;     // state dim 0..127
    const int q  = tid & 1;      // K-half 0..1

    // dt tables for both batches
    {
        const float* tp0 = t_dyn + (size_t)b0 * TT;
        const float* tp1 = t_dyn + (size_t)b1 * TT;
        for (int i = tid; i < TT; i += 256) {
            float c0 = __ldg(tp0 + i);
            float p0 = (i > 0) ? __ldg(tp0 + i - 1) : c0;
            sm.scan.dt0[i] = fmaxf(c0 - p0, 0.0f);
            float c1 = __ldg(tp1 + i);
            float p1 = (i > 0) ? __ldg(tp1 + i - 1) : c1;
            sm.scan.dt1[i] = fmaxf(c1 - p1, 0.0f);
        }
        if (tid == 0) { sm.scan.dt0[TT] = 0.0f; sm.scan.dt1[TT] = 0.0f; }
    }

    // weights: rows {j, 128+j, 256+j}, K half [64q, 64q+64) -> 96 u64
    unsigned long long Wr[32], Wu[32], Wn[32];
    {
        const ulonglong2* wr = (const ulonglong2*)(W_hh + (size_t)j * DZC + 64 * q);
        const ulonglong2* wu = (const ulonglong2*)(W_hh + (size_t)(128 + j) * DZC + 64 * q);
        const ulonglong2* wn = (const ulonglong2*)(W_hh + (size_t)(256 + j) * DZC + 64 * q);
        #pragma unroll
        for (int i = 0; i < 16; i++) {
            ulonglong2 a = wr[i]; Wr[2*i] = a.x; Wr[2*i+1] = a.y;
            ulonglong2 c = wu[i]; Wu[2*i] = c.x; Wu[2*i+1] = c.y;
            ulonglong2 d = wn[i]; Wn[2*i] = d.x; Wn[2*i+1] = d.y;
        }
    }
    const float bh_n = (q == 0) ? b_hh[256 + j] : 0.0f;  // only n-bias survives folding
    const int len0 = dyn_lens[b0];
    const int len1 = dyn_lens[b1];

    float lg  = log_gamma[j];
    float sp  = (lg > 20.0f) ? lg : log1pf(expf(lg));
    const float gje = -1.4426950408889634f * sp;

    const unsigned int* cnt0 = &g_cnt[b0 * NTBLK];
    const unsigned int* cnt1 = &g_cnt[b1 * NTBLK];

    while (ldvol_(cnt0) < 3u || ldvol_(cnt1) < 3u) { }
    __threadfence();

    // gi pointers (distance-1 prefetch)
    const float* pG0 = g_gi + (size_t)b0 * TT * GG + q * DZC + j;
    const float* pN0 = g_gi + (size_t)b0 * TT * GG + 2 * DZC + j;
    const float* pG1 = g_gi + (size_t)b1 * TT * GG + q * DZC + j;
    const float* pN1 = g_gi + (size_t)b1 * TT * GG + 2 * DZC + j;
    float gi0 = __ldg(pG0), gn0 = __ldg(pN0);
    float gi1 = __ldg(pG1), gn1 = __ldg(pN1);
    pG0 += GG; pN0 += GG; pG1 += GG; pN1 += GG;

    float* zp0 = Z_traj + (size_t)b0 * TT * DZC + j;
    float* zp1 = Z_traj + (size_t)b1 * TT * DZC + j;

    float zdj0 = z0[(size_t)b0 * DZC + j];
    float zdj1 = z0[(size_t)b1 * DZC + j];
    if (q == 0) { sm.scan.zA0[j] = zdj0; sm.scan.zA1[j] = zdj1; }

    auto step = [&](int t,
                    const float* __restrict__ zr0, float* __restrict__ zw0,
                    const float* __restrict__ zr1, float* __restrict__ zw1) {
        __syncthreads();   // z(t) visible; write buffers WAR-safe

        int tp1 = t + 1;
        if ((tp1 & (TBLK - 1)) == 0 && tp1 < TT) {
            unsigned int need = (unsigned)(tp1 >> 7);
            while (ldvol_(cnt0 + need) < 3u || ldvol_(cnt1 + need) < 3u) { }
            __threadfence();
        }
        // prefetch gi(t+1), both batches
        float gi0n = __ldg(pG0), gn0n = __ldg(pN0);
        float gi1n = __ldg(pG1), gn1n = __ldg(pN1);
        pG0 += GG; pN0 += GG; pG1 += GG; pN1 += GG;

        float edn0 = ex2f_(gje * sm.scan.dt0[t + 1]);
        float edn1 = ex2f_(gje * sm.scan.dt1[t + 1]);

        // dual-batch dot: 32 LDS.128, 192 fma2, weights reused
        const ulonglong2* zc0 = (const ulonglong2*)(zr0 + 64 * q);
        const ulonglong2* zc1 = (const ulonglong2*)(zr1 + 64 * q);
        unsigned long long Ar0 = 0, Au0 = 0, An0 = 0;
        unsigned long long Ar1 = 0, Au1 = 0, An1 = 0;
        #pragma unroll
        for (int i = 0; i < 16; i++) {
            ulonglong2 v0 = zc0[i];
            ulonglong2 v1 = zc1[i];
            fma2(Ar0, Wr[2*i], v0.x); fma2(Ar0, Wr[2*i+1], v0.y);
            fma2(Ar1, Wr[2*i], v1.x); fma2(Ar1, Wr[2*i+1], v1.y);
            fma2(Au0, Wu[2*i], v0.x); fma2(Au0, Wu[2*i+1], v0.y);
            fma2(Au1, Wu[2*i], v1.x); fma2(Au1, Wu[2*i+1], v1.y);
            fma2(An0, Wn[2*i], v0.x); fma2(An0, Wn[2*i+1], v0.y);
            fma2(An1, Wn[2*i], v1.x); fma2(An1, Wn[2*i+1], v1.y);
        }
        float a, bb;
        unpk(Ar0, a, bb); float Sr0 = a + bb;
        unpk(Au0, a, bb); float Su0 = a + bb;
        unpk(An0, a, bb); float Sn0 = a + bb;
        unpk(Ar1, a, bb); float Sr1 = a + bb;
        unpk(Au1, a, bb); float Su1 = a + bb;
        unpk(An1, a, bb); float Sn1 = a + bb;

        // inject gi (r/u bias pre-folded); n-bias on q==0
        if (q == 0) { Sr0 += gi0; Sr1 += gi1; Sn0 += bh_n; Sn1 += bh_n; }
        else        { Su0 += gi0; Su1 += gi1; }

        Sr0 += __shfl_xor_sync(0xffffffffu, Sr0, 1);
        Su0 += __shfl_xor_sync(0xffffffffu, Su0, 1);
        Sn0 += __shfl_xor_sync(0xffffffffu, Sn0, 1);
        Sr1 += __shfl_xor_sync(0xffffffffu, Sr1, 1);
        Su1 += __shfl_xor_sync(0xffffffffu, Su1, 1);
        Sn1 += __shfl_xor_sync(0xffffffffu, Sn1, 1);

        // gates + epilogue, batch 0
        float rr0 = sigmoidf_(Sr0);
        float uu0 = sigmoidf_(Su0);
        float nn0 = tanhf_(gn0 + rr0 * Sn0);
        float znew0 = nn0 + uu0 * (zdj0 - nn0);
        float zj0   = (t < len0) ? znew0 : zdj0;
        // batch 1
        float rr1 = sigmoidf_(Sr1);
        float uu1 = sigmoidf_(Su1);
        float nn1 = tanhf_(gn1 + rr1 * Sn1);
        float znew1 = nn1 + uu1 * (zdj1 - nn1);
        float zj1   = (t < len1) ? znew1 : zdj1;

        if (q == 0) { *zp0 = zj0; *zp1 = zj1; }
        zp0 += DZC; zp1 += DZC;

        zdj0 = zj0 * edn0;
        zdj1 = zj1 * edn1;
        if (q == 0) { zw0[j] = zdj0; zw1[j] = zdj1; }

        gi0 = gi0n; gn0 = gn0n;
        gi1 = gi1n; gn1 = gn1n;
    };

    for (int t = 0; t < TT; t += 2) {
        step(t,     sm.scan.zA0, sm.scan.zB0, sm.scan.zA1, sm.scan.zB1);
        step(t + 1, sm.scan.zB0, sm.scan.zA0, sm.scan.zB1, sm.scan.zA1);
    }

    // dt[TT]=0 -> final zdj == last zj
    if (q == 0) {
        z_final[(size_t)b0 * DZC + j] = zdj0;
        z_final[(size_t)b1 * DZC + j] = zdj1;
    }
}

// =====================================================================
// launch
// =====================================================================
extern "C" void kernel_launch(void* const* d_in, const int* in_sizes, int n_in,
                              void* d_out, int out_size)
{
    const float* z0        = (const float*)d_in[0];
    const float* t_dyn     = (const float*)d_in[1];
    const float* Y         = (const float*)d_in[2];
    const float* M         = (const float*)d_in[3];
    const int*   dyn_lens  = (const int*)  d_in[4];
    const float* H         = (const float*)d_in[5];
    const float* W_ih      = (const float*)d_in[6];
    const float* b_ih      = (const float*)d_in[7];
    const float* W_hh      = (const float*)d_in[8];
    const float* b_hh      = (const float*)d_in[9];
    const float* log_gamma = (const float*)d_in[10];

    float* out     = (float*)d_out;
    float* z_final = out;                       // (B, DZ)
    float* Z_traj  = out + (size_t)BB * DZC;    // (B, T, DZ)

    void* cnt_ptr = nullptr;
    cudaGetSymbolAddress(&cnt_ptr, g_cnt);
    cudaMemsetAsync(cnt_ptr, 0, sizeof(unsigned int) * BB * NTBLK);

    fused_kernel<<<SCAN_CTAS + GEMM_CTAS, 256>>>(
        z0, t_dyn, dyn_lens, Y, M, H, W_ih, b_ih, W_hh, b_hh, log_gamma,
        z_final, Z_traj);
}

// round 8
// speedup vs baseline: 1.7859x; 1.7859x over previous
#include <cuda_runtime.h>
#include <cuda_bf16.h>
#include <math.h>

// Problem constants
#define BB   32
#define TT   4096
#define DZC  128
#define NDC  32
#define DHC  128
#define GG   384            // 3*DZ
#define IND  192            // 2*ND + DH

#define TBLK      128                 // timesteps per GEMM tile
#define NTBLK     (TT / TBLK)         // 32 t-blocks per batch
#define GEMM_CTAS (NTBLK * BB * 3)    // 3072
#define SCAN_CTAS BB                  // 32

// z exchange buffer: halves padded 16 floats apart -> bank-disjoint reads
#define ZPAD 144

// ---------------- scratch (no cudaMalloc allowed) ----------------
__device__ float        g_gi[(size_t)BB * TT * GG + 2 * GG];
__device__ unsigned int g_cnt[BB * NTBLK];

// ---------------- packed fp32x2 helpers (sm_100+) ----------------
__device__ __forceinline__ void fma2(unsigned long long& d,
                                     unsigned long long a,
                                     unsigned long long b) {
    asm("fma.rn.f32x2 %0, %1, %2, %0;" : "+l"(d) : "l"(a), "l"(b));
}
__device__ __forceinline__ void add2(unsigned long long& d, unsigned long long a) {
    asm("add.rn.f32x2 %0, %0, %1;" : "+l"(d) : "l"(a));
}
__device__ __forceinline__ unsigned long long dup2(float a) {
    unsigned long long r;
    asm("mov.b64 %0, {%1, %1};" : "=l"(r) : "f"(a));
    return r;
}
__device__ __forceinline__ void unpk(unsigned long long v, float& x, float& y) {
    asm("mov.b64 {%0, %1}, %2;" : "=f"(x), "=f"(y) : "l"(v));
}
__device__ __forceinline__ float ex2f_(float x) {
    float y; asm("ex2.approx.f32 %0, %1;" : "=f"(y) : "f"(x)); return y;
}
__device__ __forceinline__ float rcpf_(float x) {
    float y; asm("rcp.approx.f32 %0, %1;" : "=f"(y) : "f"(x)); return y;
}
__device__ __forceinline__ float sigmoidf_(float x) {
    float e = ex2f_(-1.4426950408889634f * x);
    return rcpf_(1.0f + e);
}
__device__ __forceinline__ float tanhf_(float x) {
    float xc = fminf(fmaxf(x, -20.0f), 20.0f);
    float e = ex2f_(-2.8853900817779268f * xc);   // exp(-2x)
    return (1.0f - e) * rcpf_(1.0f + e);
}
__device__ __forceinline__ unsigned int ldvol_(const unsigned int* p) {
    unsigned int v;
    asm volatile("ld.volatile.global.b32 %0, [%1];" : "=r"(v) : "l"(p));
    return v;
}

// =====================================================================
// Fused kernel. blockIdx.x < 32  -> scan role (one CTA per batch)
//               blockIdx.x >= 32 -> GEMM tile role (t-block-major order)
// GEMM adds b_ih and, for r/u rows (g<256), folds in b_hh.
// =====================================================================
#define Bb 128
#define BN 128
#define BK 16

struct ScanSmem {
    float dtbuf[TT + 4];
    float zbA[ZPAD];
    float zbB[ZPAD];
};
struct GemmSmem {
    float As[2][BK][Bb];
    float Bs[2][BK][BN];
};

__global__ __launch_bounds__(256, 1) void fused_kernel(
    const float* __restrict__ z0, const float* __restrict__ t_dyn,
    const int* __restrict__ dyn_lens,
    const float* __restrict__ Y, const float* __restrict__ M,
    const float* __restrict__ H,
    const float* __restrict__ W_ih, const float* __restrict__ b_ih,
    const float* __restrict__ W_hh, const float* __restrict__ b_hh,
    const float* __restrict__ log_gamma,
    float* __restrict__ z_final, float* __restrict__ Z_traj)
{
    __shared__ __align__(16) union { ScanSmem scan; GemmSmem gemm; } sm;

    const int tid = threadIdx.x;

    if (blockIdx.x >= SCAN_CTAS) {
        // ================= GEMM role =================
        const int gidx = blockIdx.x - SCAN_CTAS;
        const int tb   = gidx / (BB * 3);
        const int rem  = gidx % (BB * 3);
        const int b    = rem / 3;
        const int gblk = rem % 3;
        const int bt0  = b * TT + tb * TBLK;
        const int g0   = gblk * BN;

        float* gi = g_gi;
        const int tx = tid & 15;
        const int ty = tid >> 4;

        unsigned long long acc[8][4];
        #pragma unroll
        for (int i = 0; i < 8; i++)
            #pragma unroll
            for (int j = 0; j < 4; j++) acc[i][j] = 0ull;

        auto loadA = [&](int stage, int kc) {
            #pragma unroll
            for (int i = 0; i < 2; i++) {
                int e  = tid + 256 * i;
                int m  = e & 127;
                int k4 = e >> 7;
                int kk = kc * BK + k4 * 4;
                int bt = bt0 + m;
                float4 v;
                if (kk < 32)       v = *(const float4*)(Y + (size_t)bt * NDC + kk);
                else if (kk < 64)  v = *(const float4*)(M + (size_t)bt * NDC + (kk - 32));
                else               v = *(const float4*)(H + (size_t)bt * DHC + (kk - 64));
                sm.gemm.As[stage][k4 * 4 + 0][m] = v.x;
                sm.gemm.As[stage][k4 * 4 + 1][m] = v.y;
                sm.gemm.As[stage][k4 * 4 + 2][m] = v.z;
                sm.gemm.As[stage][k4 * 4 + 3][m] = v.w;
            }
        };
        auto loadB = [&](int stage, int kc) {
            #pragma unroll
            for (int i = 0; i < 2; i++) {
                int e  = tid + 256 * i;
                int g  = e & 127;
                int k4 = e >> 7;
                int kk = kc * BK + k4 * 4;
                float4 v = *(const float4*)(W_ih + (size_t)(g0 + g) * IND + kk);
                sm.gemm.Bs[stage][k4 * 4 + 0][g] = v.x;
                sm.gemm.Bs[stage][k4 * 4 + 1][g] = v.y;
                sm.gemm.Bs[stage][k4 * 4 + 2][g] = v.z;
                sm.gemm.Bs[stage][k4 * 4 + 3][g] = v.w;
            }
        };

        loadA(0, 0); loadB(0, 0);
        __syncthreads();

        const int NKC = IND / BK;   // 12
        for (int kc = 0; kc < NKC; kc++) {
            int cur = kc & 1, nxt = cur ^ 1;
            if (kc + 1 < NKC) { loadA(nxt, kc + 1); loadB(nxt, kc + 1); }
            #pragma unroll
            for (int k = 0; k < BK; k++) {
                float a[8];
                *(float4*)&a[0] = *(const float4*)&sm.gemm.As[cur][k][ty * 8];
                *(float4*)&a[4] = *(const float4*)&sm.gemm.As[cur][k][ty * 8 + 4];
                unsigned long long bv[4];
                {
                    ulonglong2 b0 = *(const ulonglong2*)&sm.gemm.Bs[cur][k][tx * 8];
                    ulonglong2 b1 = *(const ulonglong2*)&sm.gemm.Bs[cur][k][tx * 8 + 4];
                    bv[0] = b0.x; bv[1] = b0.y; bv[2] = b1.x; bv[3] = b1.y;
                }
                #pragma unroll
                for (int i = 0; i < 8; i++) {
                    unsigned long long ad = dup2(a[i]);
                    fma2(acc[i][0], ad, bv[0]);
                    fma2(acc[i][1], ad, bv[1]);
                    fma2(acc[i][2], ad, bv[2]);
                    fma2(acc[i][3], ad, bv[3]);
                }
            }
            __syncthreads();
        }

        // bias: b_ih always; fold b_hh for r/u rows (g < 256)
        float bia[8];
        *(float4*)&bia[0] = *(const float4*)(b_ih + g0 + tx * 8);
        *(float4*)&bia[4] = *(const float4*)(b_ih + g0 + tx * 8 + 4);
        if (gblk < 2) {
            float bh[8];
            *(float4*)&bh[0] = *(const float4*)(b_hh + g0 + tx * 8);
            *(float4*)&bh[4] = *(const float4*)(b_hh + g0 + tx * 8 + 4);
            #pragma unroll
            for (int j = 0; j < 8; j++) bia[j] += bh[j];
        }

        #pragma unroll
        for (int i = 0; i < 8; i++) {
            float c[8];
            unpk(acc[i][0], c[0], c[1]);
            unpk(acc[i][1], c[2], c[3]);
            unpk(acc[i][2], c[4], c[5]);
            unpk(acc[i][3], c[6], c[7]);
            #pragma unroll
            for (int j = 0; j < 8; j++) c[j] += bia[j];
            int bt = bt0 + ty * 8 + i;
            float* outp = gi + (size_t)bt * GG + g0 + tx * 8;
            *(float4*)(outp)     = *(float4*)&c[0];
            *(float4*)(outp + 4) = *(float4*)&c[4];
        }

        __threadfence();
        __syncthreads();
        if (tid == 0) atomicAdd(&g_cnt[b * NTBLK + tb], 1u);
        return;
    }

    // ================= scan role =================
    const int b = blockIdx.x;
    const int j = tid >> 1;     // state dim 0..127
    const int q = tid & 1;      // K-half 0..1

    float* dtbuf = sm.scan.dtbuf;
    float* zbA   = sm.scan.zbA;
    float* zbB   = sm.scan.zbB;

    // dt[t] = max(ts[t]-ts[t-1],0), dt[0]=0, dt[TT]=0
    {
        const float* tp = t_dyn + (size_t)b * TT;
        for (int i = tid; i < TT; i += 256) {
            float cur = __ldg(tp + i);
            float prv = (i > 0) ? __ldg(tp + i - 1) : cur;
            dtbuf[i] = fmaxf(cur - prv, 0.0f);
        }
        if (tid == 0) dtbuf[TT] = 0.0f;
    }

    // weights: rows {j, 128+j, 256+j}, K half [64q, 64q+64) -> 96 u64
    unsigned long long Wr[32], Wu[32], Wn[32];
    {
        const ulonglong2* wr = (const ulonglong2*)(W_hh + (size_t)j * DZC + 64 * q);
        const ulonglong2* wu = (const ulonglong2*)(W_hh + (size_t)(128 + j) * DZC + 64 * q);
        const ulonglong2* wn = (const ulonglong2*)(W_hh + (size_t)(256 + j) * DZC + 64 * q);
        #pragma unroll
        for (int i = 0; i < 16; i++) {
            ulonglong2 a = wr[i]; Wr[2*i] = a.x; Wr[2*i+1] = a.y;
            ulonglong2 c = wu[i]; Wu[2*i] = c.x; Wu[2*i+1] = c.y;
            ulonglong2 d = wn[i]; Wn[2*i] = d.x; Wn[2*i+1] = d.y;
        }
    }
    const float bh_n = (q == 0) ? b_hh[256 + j] : 0.0f;  // r/u bias folded in GEMM
    const int   len  = dyn_lens[b];

    float lg  = log_gamma[j];
    float sp  = (lg > 20.0f) ? lg : log1pf(expf(lg));   // softplus
    const float gje = -1.4426950408889634f * sp;

    const unsigned int* cntp = &g_cnt[b * NTBLK];

    // padded z layout: dim k at index k + 16*(k>=64)
    const int wj = j + ((j >> 6) << 4);

    while (ldvol_(cntp) < 3u) { }
    __threadfence();

    // gi streams, distance-1 prefetch
    const float* pG = g_gi + (size_t)b * TT * GG + q * DZC + j;
    const float* pN = g_gi + (size_t)b * TT * GG + 2 * DZC + j;
    float gi_c = __ldg(pG);
    float gn_c = __ldg(pN);
    pG += GG; pN += GG;

    float* zp = Z_traj + (size_t)b * TT * DZC + j;

    float zdj = z0[(size_t)b * DZC + j];
    if (q == 0) zbA[wj] = zdj;

    auto step = [&](int t, const float* __restrict__ zr, float* __restrict__ zw) {
        __syncthreads();   // z(t) visible; zw WAR-safe (double buffer)

        int tn = t + 1;
        if ((tn & (TBLK - 1)) == 0 && tn < TT) {
            unsigned int need = (unsigned)(tn >> 7);
            while (ldvol_(cntp + need) < 3u) { }
            __threadfence();
        }
        // prefetch gi(t+1)
        float giN = __ldg(pG), gnN = __ldg(pN);
        pG += GG; pN += GG;

        float edn = ex2f_(gje * dtbuf[tn]);   // decay for t+1

        // dot over K-half: hand-pipelined depth-2 LDS, 96 fma2, 6 accs
        const ulonglong2* zc = (const ulonglong2*)(zr + (q ? 80 : 0));
        unsigned long long ar0 = 0, ar1 = 0, au0 = 0, au1 = 0, an0 = 0, an1 = 0;
        ulonglong2 v0 = zc[0];
        ulonglong2 v1 = zc[1];
        #pragma unroll
        for (int i = 0; i < 16; i += 2) {
            ulonglong2 n0, n1;
            if (i + 2 < 16) { n0 = zc[i + 2]; n1 = zc[i + 3]; }
            fma2(ar0, Wr[2*i],   v0.x); fma2(ar0, Wr[2*i+1], v0.y);
            fma2(au0, Wu[2*i],   v0.x); fma2(au0, Wu[2*i+1], v0.y);
            fma2(an0, Wn[2*i],   v0.x); fma2(an0, Wn[2*i+1], v0.y);
            fma2(ar1, Wr[2*i+2], v1.x); fma2(ar1, Wr[2*i+3], v1.y);
            fma2(au1, Wu[2*i+2], v1.x); fma2(au1, Wu[2*i+3], v1.y);
            fma2(an1, Wn[2*i+2], v1.x); fma2(an1, Wn[2*i+3], v1.y);
            v0 = n0; v1 = n1;
        }
        add2(ar0, ar1); add2(au0, au1); add2(an0, an1);
        float x, y;
        unpk(ar0, x, y); float Sr = x + y;
        unpk(au0, x, y); float Su = x + y;
        unpk(an0, x, y); float Sn = x + y;

        // inject gi (r/u bias pre-folded into gi); n-bias on q==0
        if (q == 0) { Sr += gi_c; Sn += bh_n; }
        else        { Su += gi_c; }

        Sr += __shfl_xor_sync(0xffffffffu, Sr, 1);
        Su += __shfl_xor_sync(0xffffffffu, Su, 1);
        Sn += __shfl_xor_sync(0xffffffffu, Sn, 1);

        // gates + epilogue
        float rr = sigmoidf_(Sr);
        float uu = sigmoidf_(Su);
        float nn = tanhf_(gn_c + rr * Sn);
        float znew = nn + uu * (zdj - nn);
        // speculate decay on both branches, select late
        float zdA = znew * edn;
        float zdB = zdj  * edn;
        bool  act = (t < len);
        float zjout = act ? znew : zdj;
        float zdn   = act ? zdA  : zdB;
        if (q == 0) zw[wj] = zdn;     // critical exchange first
        if (q == 0) *zp = zjout;      // trajectory store off-path
        zp += DZC;
        zdj = zdn;

        gi_c = giN; gn_c = gnN;
    };

    for (int t = 0; t < TT; t += 2) {
        step(t,     zbA, zbB);
        step(t + 1, zbB, zbA);
    }

    // dt[TT]=0 -> final zdj == last zj
    if (q == 0) z_final[(size_t)b * DZC + j] = zdj;
}

// =====================================================================
// launch
// =====================================================================
extern "C" void kernel_launch(void* const* d_in, const int* in_sizes, int n_in,
                              void* d_out, int out_size)
{
    const float* z0        = (const float*)d_in[0];
    const float* t_dyn     = (const float*)d_in[1];
    const float* Y         = (const float*)d_in[2];
    const float* M         = (const float*)d_in[3];
    const int*   dyn_lens  = (const int*)  d_in[4];
    const float* H         = (const float*)d_in[5];
    const float* W_ih      = (const float*)d_in[6];
    const float* b_ih      = (const float*)d_in[7];
    const float* W_hh      = (const float*)d_in[8];
    const float* b_hh      = (const float*)d_in[9];
    const float* log_gamma = (const float*)d_in[10];

    float* out     = (float*)d_out;
    float* z_final = out;                       // (B, DZ)
    float* Z_traj  = out + (size_t)BB * DZC;    // (B, T, DZ)

    void* cnt_ptr = nullptr;
    cudaGetSymbolAddress(&cnt_ptr, g_cnt);
    cudaMemsetAsync(cnt_ptr, 0, sizeof(unsigned int) * BB * NTBLK);

    fused_kernel<<<SCAN_CTAS + GEMM_CTAS, 256>>>(
        z0, t_dyn, dyn_lens, Y, M, H, W_ih, b_ih, W_hh, b_hh, log_gamma,
        z_final, Z_traj);
}

// round 9
// speedup vs baseline: 1.8358x; 1.0279x over previous
#include <cuda_runtime.h>
#include <cuda_bf16.h>
#include <math.h>

// Problem constants
#define BB   32
#define TT   4096
#define DZC  128
#define NDC  32
#define DHC  128
#define GG   384            // 3*DZ
#define IND  192            // 2*ND + DH

#define TBLK      128                 // timesteps per GEMM tile
#define NTBLK     (TT / TBLK)         // 32 t-blocks per batch
#define GEMM_CTAS (NTBLK * BB * 3)    // 3072
#define SCAN_CTAS BB                  // 32

// z exchange buffer: halves padded 16 floats apart -> bank-disjoint reads
#define ZPAD 144

// ---------------- scratch (no cudaMalloc allowed) ----------------
__device__ float        g_gi[(size_t)BB * TT * GG + 2 * GG];
__device__ unsigned int g_cnt[BB * NTBLK];

// ---------------- packed fp32x2 helpers (sm_100+) ----------------
__device__ __forceinline__ void fma2(unsigned long long& d,
                                     unsigned long long a,
                                     unsigned long long b) {
    asm("fma.rn.f32x2 %0, %1, %2, %0;" : "+l"(d) : "l"(a), "l"(b));
}
__device__ __forceinline__ void add2(unsigned long long& d, unsigned long long a) {
    asm("add.rn.f32x2 %0, %0, %1;" : "+l"(d) : "l"(a));
}
__device__ __forceinline__ unsigned long long dup2(float a) {
    unsigned long long r;
    asm("mov.b64 %0, {%1, %1};" : "=l"(r) : "f"(a));
    return r;
}
__device__ __forceinline__ void unpk(unsigned long long v, float& x, float& y) {
    asm("mov.b64 {%0, %1}, %2;" : "=f"(x), "=f"(y) : "l"(v));
}
__device__ __forceinline__ float ex2f_(float x) {
    float y; asm("ex2.approx.f32 %0, %1;" : "=f"(y) : "f"(x)); return y;
}
__device__ __forceinline__ float rcpf_(float x) {
    float y; asm("rcp.approx.f32 %0, %1;" : "=f"(y) : "f"(x)); return y;
}
__device__ __forceinline__ float sigmoidf_(float x) {
    float e = ex2f_(-1.4426950408889634f * x);
    return rcpf_(1.0f + e);
}
__device__ __forceinline__ float tanhf_(float x) {
    float xc = fminf(fmaxf(x, -20.0f), 20.0f);
    float e = ex2f_(-2.8853900817779268f * xc);   // exp(-2x)
    return (1.0f - e) * rcpf_(1.0f + e);
}
__device__ __forceinline__ unsigned int ldvol_(const unsigned int* p) {
    unsigned int v;
    asm volatile("ld.volatile.global.b32 %0, [%1];" : "=r"(v) : "l"(p));
    return v;
}

// =====================================================================
// Fused kernel. blockIdx.x < 32  -> scan role (one CTA per batch)
//               blockIdx.x >= 32 -> GEMM tile role (t-block-major order)
// GEMM adds b_ih and, for r/u rows (g<256), folds in b_hh.
// =====================================================================
#define Bb 128
#define BN 128
#define BK 16

struct ScanSmem {
    float dtbuf[TT + 4];
    float zbA[ZPAD];
    float zbB[ZPAD];
};
struct GemmSmem {
    float As[2][BK][Bb];
    float Bs[2][BK][BN];
};

__global__ __launch_bounds__(256, 1) void fused_kernel(
    const float* __restrict__ z0, const float* __restrict__ t_dyn,
    const int* __restrict__ dyn_lens,
    const float* __restrict__ Y, const float* __restrict__ M,
    const float* __restrict__ H,
    const float* __restrict__ W_ih, const float* __restrict__ b_ih,
    const float* __restrict__ W_hh, const float* __restrict__ b_hh,
    const float* __restrict__ log_gamma,
    float* __restrict__ z_final, float* __restrict__ Z_traj)
{
    __shared__ __align__(16) union { ScanSmem scan; GemmSmem gemm; } sm;

    const int tid = threadIdx.x;

    if (blockIdx.x >= SCAN_CTAS) {
        // ================= GEMM role =================
        const int gidx = blockIdx.x - SCAN_CTAS;
        const int tb   = gidx / (BB * 3);
        const int rem  = gidx % (BB * 3);
        const int b    = rem / 3;
        const int gblk = rem % 3;
        const int bt0  = b * TT + tb * TBLK;
        const int g0   = gblk * BN;

        float* gi = g_gi;
        const int tx = tid & 15;
        const int ty = tid >> 4;

        unsigned long long acc[8][4];
        #pragma unroll
        for (int i = 0; i < 8; i++)
            #pragma unroll
            for (int j = 0; j < 4; j++) acc[i][j] = 0ull;

        auto loadA = [&](int stage, int kc) {
            #pragma unroll
            for (int i = 0; i < 2; i++) {
                int e  = tid + 256 * i;
                int m  = e & 127;
                int k4 = e >> 7;
                int kk = kc * BK + k4 * 4;
                int bt = bt0 + m;
                float4 v;
                if (kk < 32)       v = *(const float4*)(Y + (size_t)bt * NDC + kk);
                else if (kk < 64)  v = *(const float4*)(M + (size_t)bt * NDC + (kk - 32));
                else               v = *(const float4*)(H + (size_t)bt * DHC + (kk - 64));
                sm.gemm.As[stage][k4 * 4 + 0][m] = v.x;
                sm.gemm.As[stage][k4 * 4 + 1][m] = v.y;
                sm.gemm.As[stage][k4 * 4 + 2][m] = v.z;
                sm.gemm.As[stage][k4 * 4 + 3][m] = v.w;
            }
        };
        auto loadB = [&](int stage, int kc) {
            #pragma unroll
            for (int i = 0; i < 2; i++) {
                int e  = tid + 256 * i;
                int g  = e & 127;
                int k4 = e >> 7;
                int kk = kc * BK + k4 * 4;
                float4 v = *(const float4*)(W_ih + (size_t)(g0 + g) * IND + kk);
                sm.gemm.Bs[stage][k4 * 4 + 0][g] = v.x;
                sm.gemm.Bs[stage][k4 * 4 + 1][g] = v.y;
                sm.gemm.Bs[stage][k4 * 4 + 2][g] = v.z;
                sm.gemm.Bs[stage][k4 * 4 + 3][g] = v.w;
            }
        };

        loadA(0, 0); loadB(0, 0);
        __syncthreads();

        const int NKC = IND / BK;   // 12
        for (int kc = 0; kc < NKC; kc++) {
            int cur = kc & 1, nxt = cur ^ 1;
            if (kc + 1 < NKC) { loadA(nxt, kc + 1); loadB(nxt, kc + 1); }
            #pragma unroll
            for (int k = 0; k < BK; k++) {
                float a[8];
                *(float4*)&a[0] = *(const float4*)&sm.gemm.As[cur][k][ty * 8];
                *(float4*)&a[4] = *(const float4*)&sm.gemm.As[cur][k][ty * 8 + 4];
                unsigned long long bv[4];
                {
                    ulonglong2 b0 = *(const ulonglong2*)&sm.gemm.Bs[cur][k][tx * 8];
                    ulonglong2 b1 = *(const ulonglong2*)&sm.gemm.Bs[cur][k][tx * 8 + 4];
                    bv[0] = b0.x; bv[1] = b0.y; bv[2] = b1.x; bv[3] = b1.y;
                }
                #pragma unroll
                for (int i = 0; i < 8; i++) {
                    unsigned long long ad = dup2(a[i]);
                    fma2(acc[i][0], ad, bv[0]);
                    fma2(acc[i][1], ad, bv[1]);
                    fma2(acc[i][2], ad, bv[2]);
                    fma2(acc[i][3], ad, bv[3]);
                }
            }
            __syncthreads();
        }

        // bias: b_ih always; fold b_hh for r/u rows (g < 256)
        float bia[8];
        *(float4*)&bia[0] = *(const float4*)(b_ih + g0 + tx * 8);
        *(float4*)&bia[4] = *(const float4*)(b_ih + g0 + tx * 8 + 4);
        if (gblk < 2) {
            float bh[8];
            *(float4*)&bh[0] = *(const float4*)(b_hh + g0 + tx * 8);
            *(float4*)&bh[4] = *(const float4*)(b_hh + g0 + tx * 8 + 4);
            #pragma unroll
            for (int j = 0; j < 8; j++) bia[j] += bh[j];
        }

        #pragma unroll
        for (int i = 0; i < 8; i++) {
            float c[8];
            unpk(acc[i][0], c[0], c[1]);
            unpk(acc[i][1], c[2], c[3]);
            unpk(acc[i][2], c[4], c[5]);
            unpk(acc[i][3], c[6], c[7]);
            #pragma unroll
            for (int j = 0; j < 8; j++) c[j] += bia[j];
            int bt = bt0 + ty * 8 + i;
            float* outp = gi + (size_t)bt * GG + g0 + tx * 8;
            *(float4*)(outp)     = *(float4*)&c[0];
            *(float4*)(outp + 4) = *(float4*)&c[4];
        }

        __threadfence();
        __syncthreads();
        if (tid == 0) atomicAdd(&g_cnt[b * NTBLK + tb], 1u);
        return;
    }

    // ================= scan role =================
    const int b = blockIdx.x;
    const int j = tid >> 1;     // state dim 0..127
    const int q = tid & 1;      // K-half 0..1

    float* dtbuf = sm.scan.dtbuf;
    float* zbA   = sm.scan.zbA;
    float* zbB   = sm.scan.zbB;

    // dt[t] = max(ts[t]-ts[t-1],0), dt[0]=0, dt[TT]=0
    {
        const float* tp = t_dyn + (size_t)b * TT;
        for (int i = tid; i < TT; i += 256) {
            float cur = __ldg(tp + i);
            float prv = (i > 0) ? __ldg(tp + i - 1) : cur;
            dtbuf[i] = fmaxf(cur - prv, 0.0f);
        }
        if (tid == 0) dtbuf[TT] = 0.0f;
    }

    // weights: rows {j, 128+j, 256+j}, K half [64q, 64q+64) -> 96 u64
    unsigned long long Wr[32], Wu[32], Wn[32];
    {
        const ulonglong2* wr = (const ulonglong2*)(W_hh + (size_t)j * DZC + 64 * q);
        const ulonglong2* wu = (const ulonglong2*)(W_hh + (size_t)(128 + j) * DZC + 64 * q);
        const ulonglong2* wn = (const ulonglong2*)(W_hh + (size_t)(256 + j) * DZC + 64 * q);
        #pragma unroll
        for (int i = 0; i < 16; i++) {
            ulonglong2 a = wr[i]; Wr[2*i] = a.x; Wr[2*i+1] = a.y;
            ulonglong2 c = wu[i]; Wu[2*i] = c.x; Wu[2*i+1] = c.y;
            ulonglong2 d = wn[i]; Wn[2*i] = d.x; Wn[2*i+1] = d.y;
        }
    }
    const float bh_n = (q == 0) ? b_hh[256 + j] : 0.0f;  // r/u bias folded in GEMM
    const int   L    = dyn_lens[b];                      // active steps (>=1)

    float lg  = log_gamma[j];
    float sp  = (lg > 20.0f) ? lg : log1pf(expf(lg));   // softplus
    const float gje = -1.4426950408889634f * sp;

    const unsigned int* cntp = &g_cnt[b * NTBLK];

    // padded z layout: dim k at index k + 16*(k>=64)
    const int wj = j + ((j >> 6) << 4);

    while (ldvol_(cntp) < 3u) { }
    __threadfence();

    // gi streams, distance-1 prefetch; pG/pN point at row t+1 at step t entry
    const float* pG = g_gi + (size_t)b * TT * GG + q * DZC + j;
    const float* pN = g_gi + (size_t)b * TT * GG + 2 * DZC + j;
    float gi_c = __ldg(pG);
    float gn_c = __ldg(pN);
    pG += GG; pN += GG;

    float* zp = Z_traj + (size_t)b * TT * DZC + j;   // row t at pair entry

    float zdj = z0[(size_t)b * DZC + j];
    float zlast = zdj;
    if (q == 0) zbA[wj] = zdj;

    // one active step; tn = t+1; offsets are call-site literals
    auto step = [&](int tn, int offG, int offZ, bool chk,
                    const float* __restrict__ zr, float* __restrict__ zw) {
        __syncthreads();   // z(t) visible; zw WAR-safe (double buffer)

        if (chk && (tn & (TBLK - 1)) == 0 && tn < L) {
            unsigned int need = (unsigned)(tn >> 7);
            while (ldvol_(cntp + need) < 3u) { }
            __threadfence();
        }
        // prefetch gi(tn) (value unused if tn >= L; memory always valid)
        float giN = __ldg(pG + offG), gnN = __ldg(pN + offG);

        float edn = ex2f_(gje * dtbuf[tn]);   // decay t -> t+1

        // dot over K-half: hand-pipelined depth-2 LDS, 96 fma2, 6 accs
        const ulonglong2* zc = (const ulonglong2*)(zr + (q ? 80 : 0));
        unsigned long long ar0 = 0, ar1 = 0, au0 = 0, au1 = 0, an0 = 0, an1 = 0;
        ulonglong2 v0 = zc[0];
        ulonglong2 v1 = zc[1];
        #pragma unroll
        for (int i = 0; i < 16; i += 2) {
            ulonglong2 n0, n1;
            if (i + 2 < 16) { n0 = zc[i + 2]; n1 = zc[i + 3]; }
            fma2(ar0, Wr[2*i],   v0.x); fma2(ar0, Wr[2*i+1], v0.y);
            fma2(au0, Wu[2*i],   v0.x); fma2(au0, Wu[2*i+1], v0.y);
            fma2(an0, Wn[2*i],   v0.x); fma2(an0, Wn[2*i+1], v0.y);
            fma2(ar1, Wr[2*i+2], v1.x); fma2(ar1, Wr[2*i+3], v1.y);
            fma2(au1, Wu[2*i+2], v1.x); fma2(au1, Wu[2*i+3], v1.y);
            fma2(an1, Wn[2*i+2], v1.x); fma2(an1, Wn[2*i+3], v1.y);
            v0 = n0; v1 = n1;
        }
        add2(ar0, ar1); add2(au0, au1); add2(an0, an1);
        float x, y;
        unpk(ar0, x, y); float Sr = x + y;
        unpk(au0, x, y); float Su = x + y;
        unpk(an0, x, y); float Sn = x + y;

        if (q == 0) { Sr += gi_c; Sn += bh_n; }
        else        { Su += gi_c; }

        Sr += __shfl_xor_sync(0xffffffffu, Sr, 1);
        Su += __shfl_xor_sync(0xffffffffu, Su, 1);
        Sn += __shfl_xor_sync(0xffffffffu, Sn, 1);

        float rr = sigmoidf_(Sr);
        float uu = sigmoidf_(Su);
        float nn = tanhf_(gn_c + rr * Sn);
        float znew = nn + uu * (zdj - nn);
        float zd   = znew * edn;
        if (q == 0) { zw[wj] = zd; *(zp + offZ) = znew; }
        zdj   = zd;
        zlast = znew;

        gi_c = giN; gn_c = gnN;
    };

    int t = 0;
    while (t + 2 <= L) {
        step(t + 1, 0,  0,   false, zbA, zbB);
        step(t + 2, GG, DZC, true,  zbB, zbA);
        pG += 2 * GG; pN += 2 * GG; zp += 2 * DZC;
        t += 2;
    }
    if (t < L) {   // leftover odd step; parity: read zbA
        step(t + 1, 0, 0, false, zbA, zbB);
        t += 1;
    }

    // closed-form inactive tail: z_out(k) = z_{L-1} * exp(-gamma*(ts[k]-ts[L-1]))
    {
        const float* tsrc = t_dyn + (size_t)b * TT;
        float tl = __ldg(tsrc + (L - 1));
        float zl = zlast;
        if (q == 0) {
            float tend = __ldg(tsrc + (TT - 1));
            z_final[(size_t)b * DZC + j] = zl * ex2f_(gje * (tend - tl));
        }
        float* zob = Z_traj + (size_t)b * TT * DZC + j;
        for (int k = L + q; k < TT; k += 2) {
            float v = zl * ex2f_(gje * (__ldg(tsrc + k) - tl));
            zob[(size_t)k * DZC] = v;
        }
    }
}

// =====================================================================
// launch
// =====================================================================
extern "C" void kernel_launch(void* const* d_in, const int* in_sizes, int n_in,
                              void* d_out, int out_size)
{
    const float* z0        = (const float*)d_in[0];
    const float* t_dyn     = (const float*)d_in[1];
    const float* Y         = (const float*)d_in[2];
    const float* M         = (const float*)d_in[3];
    const int*   dyn_lens  = (const int*)  d_in[4];
    const float* H         = (const float*)d_in[5];
    const float* W_ih      = (const float*)d_in[6];
    const float* b_ih      = (const float*)d_in[7];
    const float* W_hh      = (const float*)d_in[8];
    const float* b_hh      = (const float*)d_in[9];
    const float* log_gamma = (const float*)d_in[10];

    float* out     = (float*)d_out;
    float* z_final = out;                       // (B, DZ)
    float* Z_traj  = out + (size_t)BB * DZC;    // (B, T, DZ)

    void* cnt_ptr = nullptr;
    cudaGetSymbolAddress(&cnt_ptr, g_cnt);
    cudaMemsetAsync(cnt_ptr, 0, sizeof(unsigned int) * BB * NTBLK);

    fused_kernel<<<SCAN_CTAS + GEMM_CTAS, 256>>>(
        z0, t_dyn, dyn_lens, Y, M, H, W_ih, b_ih, W_hh, b_hh, log_gamma,
        z_final, Z_traj);
}

// round 10
// speedup vs baseline: 2.2176x; 1.2080x over previous
#include <cuda_runtime.h>
#include <cuda_bf16.h>
#include <math.h>

// Problem constants
#define BB   32
#define TT   4096
#define DZC  128
#define NDC  32
#define DHC  128
#define GG   384            // 3*DZ
#define IND  192            // 2*ND + DH

#define TBLK      128                 // timesteps per GEMM tile
#define NTBLK     (TT / TBLK)         // 32 t-blocks per batch
#define GEMM_CTAS (NTBLK * BB * 3)    // 3072
#define SCAN_CTAS BB                  // 32

// z exchange buffer: halves padded 16 floats apart -> bank-disjoint reads
#define ZPAD 144

// ---------------- scratch (no cudaMalloc allowed) ----------------
__device__ float        g_gi[(size_t)BB * TT * GG + 2 * GG];
__device__ unsigned int g_cnt[BB * NTBLK];

// ---------------- packed fp32x2 helpers (sm_100+) ----------------
__device__ __forceinline__ void fma2(unsigned long long& d,
                                     unsigned long long a,
                                     unsigned long long b) {
    asm("fma.rn.f32x2 %0, %1, %2, %0;" : "+l"(d) : "l"(a), "l"(b));
}
__device__ __forceinline__ void add2(unsigned long long& d, unsigned long long a) {
    asm("add.rn.f32x2 %0, %0, %1;" : "+l"(d) : "l"(a));
}
__device__ __forceinline__ unsigned long long dup2(float a) {
    unsigned long long r;
    asm("mov.b64 %0, {%1, %1};" : "=l"(r) : "f"(a));
    return r;
}
__device__ __forceinline__ unsigned long long pack2(float x, float y) {
    unsigned long long r;
    asm("mov.b64 %0, {%1, %2};" : "=l"(r) : "f"(x), "f"(y));
    return r;
}
__device__ __forceinline__ void unpk(unsigned long long v, float& x, float& y) {
    asm("mov.b64 {%0, %1}, %2;" : "=f"(x), "=f"(y) : "l"(v));
}
__device__ __forceinline__ float ex2f_(float x) {
    float y; asm("ex2.approx.f32 %0, %1;" : "=f"(y) : "f"(x)); return y;
}
__device__ __forceinline__ float rcpf_(float x) {
    float y; asm("rcp.approx.f32 %0, %1;" : "=f"(y) : "f"(x)); return y;
}
__device__ __forceinline__ float tanhap_(float x) {
    float y; asm("tanh.approx.f32 %0, %1;" : "=f"(y) : "f"(x)); return y;
}
__device__ __forceinline__ float sigmoidf_(float x) {   // precise path (u gate)
    float e = ex2f_(-1.4426950408889634f * x);
    return rcpf_(1.0f + e);
}
__device__ __forceinline__ unsigned int ldvol_(const unsigned int* p) {
    unsigned int v;
    asm volatile("ld.volatile.global.b32 %0, [%1];" : "=r"(v) : "l"(p));
    return v;
}

// =====================================================================
// Fused kernel. blockIdx.x < 32  -> scan role (one CTA per batch)
//               blockIdx.x >= 32 -> GEMM tile role (t-block-major order)
// GEMM adds b_ih; folds b_hh for r/u rows; r rows (gblk 0) prescaled 0.5
// to match rr = 0.5 + 0.5*tanh(0.5*x).
// =====================================================================
#define Bb 128
#define BN 128
#define BK 16

struct ScanSmem {
    float dtbuf[TT + 4];
    float zbA[ZPAD];
    float zbB[ZPAD];
};
struct GemmSmem {
    float As[2][BK][Bb];
    float Bs[2][BK][BN];
};

__global__ __launch_bounds__(256, 1) void fused_kernel(
    const float* __restrict__ z0, const float* __restrict__ t_dyn,
    const int* __restrict__ dyn_lens,
    const float* __restrict__ Y, const float* __restrict__ M,
    const float* __restrict__ H,
    const float* __restrict__ W_ih, const float* __restrict__ b_ih,
    const float* __restrict__ W_hh, const float* __restrict__ b_hh,
    const float* __restrict__ log_gamma,
    float* __restrict__ z_final, float* __restrict__ Z_traj)
{
    __shared__ __align__(16) union { ScanSmem scan; GemmSmem gemm; } sm;

    const int tid = threadIdx.x;

    if (blockIdx.x >= SCAN_CTAS) {
        // ================= GEMM role =================
        const int gidx = blockIdx.x - SCAN_CTAS;
        const int tb   = gidx / (BB * 3);
        const int rem  = gidx % (BB * 3);
        const int b    = rem / 3;
        const int gblk = rem % 3;
        const int bt0  = b * TT + tb * TBLK;
        const int g0   = gblk * BN;
        const float wscale = (gblk == 0) ? 0.5f : 1.0f;   // r-row prescale

        float* gi = g_gi;
        const int tx = tid & 15;
        const int ty = tid >> 4;

        unsigned long long acc[8][4];
        #pragma unroll
        for (int i = 0; i < 8; i++)
            #pragma unroll
            for (int j = 0; j < 4; j++) acc[i][j] = 0ull;

        auto loadA = [&](int stage, int kc) {
            #pragma unroll
            for (int i = 0; i < 2; i++) {
                int e  = tid + 256 * i;
                int m  = e & 127;
                int k4 = e >> 7;
                int kk = kc * BK + k4 * 4;
                int bt = bt0 + m;
                float4 v;
                if (kk < 32)       v = *(const float4*)(Y + (size_t)bt * NDC + kk);
                else if (kk < 64)  v = *(const float4*)(M + (size_t)bt * NDC + (kk - 32));
                else               v = *(const float4*)(H + (size_t)bt * DHC + (kk - 64));
                sm.gemm.As[stage][k4 * 4 + 0][m] = v.x;
                sm.gemm.As[stage][k4 * 4 + 1][m] = v.y;
                sm.gemm.As[stage][k4 * 4 + 2][m] = v.z;
                sm.gemm.As[stage][k4 * 4 + 3][m] = v.w;
            }
        };
        auto loadB = [&](int stage, int kc) {
            #pragma unroll
            for (int i = 0; i < 2; i++) {
                int e  = tid + 256 * i;
                int g  = e & 127;
                int k4 = e >> 7;
                int kk = kc * BK + k4 * 4;
                float4 v = *(const float4*)(W_ih + (size_t)(g0 + g) * IND + kk);
                sm.gemm.Bs[stage][k4 * 4 + 0][g] = v.x * wscale;
                sm.gemm.Bs[stage][k4 * 4 + 1][g] = v.y * wscale;
                sm.gemm.Bs[stage][k4 * 4 + 2][g] = v.z * wscale;
                sm.gemm.Bs[stage][k4 * 4 + 3][g] = v.w * wscale;
            }
        };

        loadA(0, 0); loadB(0, 0);
        __syncthreads();

        const int NKC = IND / BK;   // 12
        for (int kc = 0; kc < NKC; kc++) {
            int cur = kc & 1, nxt = cur ^ 1;
            if (kc + 1 < NKC) { loadA(nxt, kc + 1); loadB(nxt, kc + 1); }
            #pragma unroll
            for (int k = 0; k < BK; k++) {
                float a[8];
                *(float4*)&a[0] = *(const float4*)&sm.gemm.As[cur][k][ty * 8];
                *(float4*)&a[4] = *(const float4*)&sm.gemm.As[cur][k][ty * 8 + 4];
                unsigned long long bv[4];
                {
                    ulonglong2 b0 = *(const ulonglong2*)&sm.gemm.Bs[cur][k][tx * 8];
                    ulonglong2 b1 = *(const ulonglong2*)&sm.gemm.Bs[cur][k][tx * 8 + 4];
                    bv[0] = b0.x; bv[1] = b0.y; bv[2] = b1.x; bv[3] = b1.y;
                }
                #pragma unroll
                for (int i = 0; i < 8; i++) {
                    unsigned long long ad = dup2(a[i]);
                    fma2(acc[i][0], ad, bv[0]);
                    fma2(acc[i][1], ad, bv[1]);
                    fma2(acc[i][2], ad, bv[2]);
                    fma2(acc[i][3], ad, bv[3]);
                }
            }
            __syncthreads();
        }

        // bias: b_ih; fold b_hh for r/u rows; r rows scaled 0.5
        float bia[8];
        *(float4*)&bia[0] = *(const float4*)(b_ih + g0 + tx * 8);
        *(float4*)&bia[4] = *(const float4*)(b_ih + g0 + tx * 8 + 4);
        if (gblk < 2) {
            float bh[8];
            *(float4*)&bh[0] = *(const float4*)(b_hh + g0 + tx * 8);
            *(float4*)&bh[4] = *(const float4*)(b_hh + g0 + tx * 8 + 4);
            #pragma unroll
            for (int j = 0; j < 8; j++) bia[j] = (bia[j] + bh[j]) * wscale;
        }

        #pragma unroll
        for (int i = 0; i < 8; i++) {
            float c[8];
            unpk(acc[i][0], c[0], c[1]);
            unpk(acc[i][1], c[2], c[3]);
            unpk(acc[i][2], c[4], c[5]);
            unpk(acc[i][3], c[6], c[7]);
            #pragma unroll
            for (int j = 0; j < 8; j++) c[j] += bia[j];
            int bt = bt0 + ty * 8 + i;
            float* outp = gi + (size_t)bt * GG + g0 + tx * 8;
            *(float4*)(outp)     = *(float4*)&c[0];
            *(float4*)(outp + 4) = *(float4*)&c[4];
        }

        __threadfence();
        __syncthreads();
        if (tid == 0) atomicAdd(&g_cnt[b * NTBLK + tb], 1u);
        return;
    }

    // ================= scan role =================
    const int b = blockIdx.x;
    const int j = tid >> 1;     // state dim 0..127
    const int q = tid & 1;      // K-half 0..1

    float* dtbuf = sm.scan.dtbuf;
    float* zbA   = sm.scan.zbA;
    float* zbB   = sm.scan.zbB;

    // dt[t] = max(ts[t]-ts[t-1],0), dt[0]=0, dt[TT]=0
    {
        const float* tp = t_dyn + (size_t)b * TT;
        for (int i = tid; i < TT; i += 256) {
            float cur = __ldg(tp + i);
            float prv = (i > 0) ? __ldg(tp + i - 1) : cur;
            dtbuf[i] = fmaxf(cur - prv, 0.0f);
        }
        if (tid == 0) dtbuf[TT] = 0.0f;
    }

    // weights: rows {j, 128+j, 256+j}, K half [64q, 64q+64) -> 96 u64
    // Wr prescaled by 0.5 (matches rr = 0.5 + 0.5*tanh(0.5*x))
    unsigned long long Wr[32], Wu[32], Wn[32];
    {
        const float4* wr = (const float4*)(W_hh + (size_t)j * DZC + 64 * q);
        const float4* wu = (const float4*)(W_hh + (size_t)(128 + j) * DZC + 64 * q);
        const float4* wn = (const float4*)(W_hh + (size_t)(256 + j) * DZC + 64 * q);
        #pragma unroll
        for (int i = 0; i < 16; i++) {
            float4 a = wr[i];
            Wr[2*i]   = pack2(a.x * 0.5f, a.y * 0.5f);
            Wr[2*i+1] = pack2(a.z * 0.5f, a.w * 0.5f);
            float4 c = wu[i];
            Wu[2*i]   = pack2(c.x, c.y);
            Wu[2*i+1] = pack2(c.z, c.w);
            float4 d = wn[i];
            Wn[2*i]   = pack2(d.x, d.y);
            Wn[2*i+1] = pack2(d.z, d.w);
        }
    }
    const float bh_n = (q == 0) ? b_hh[256 + j] : 0.0f;  // r/u bias folded in GEMM
    const int   L    = dyn_lens[b];                      // active steps (>=1)

    float lg  = log_gamma[j];
    float sp  = (lg > 20.0f) ? lg : log1pf(expf(lg));   // softplus
    const float gje = -1.4426950408889634f * sp;

    const unsigned int* cntp = &g_cnt[b * NTBLK];

    // padded z layout: dim k at index k + 16*(k>=64)
    const int wj = j + ((j >> 6) << 4);

    while (ldvol_(cntp) < 3u) { }
    __threadfence();

    // gi streams, distance-1 prefetch; pG/pN point at row t+1 at step t entry
    const float* pG = g_gi + (size_t)b * TT * GG + q * DZC + j;
    const float* pN = g_gi + (size_t)b * TT * GG + 2 * DZC + j;
    float gi_c = __ldg(pG);
    float gn_c = __ldg(pN);
    pG += GG; pN += GG;

    float* zp = Z_traj + (size_t)b * TT * DZC + j;   // row t at pair entry

    float zdj = z0[(size_t)b * DZC + j];
    float zlast = zdj;
    if (q == 0) zbA[wj] = zdj;

    // one active step; tn = t+1; offsets are call-site literals
    auto step = [&](int tn, int offG, int offZ, bool chk,
                    const float* __restrict__ zr, float* __restrict__ zw) {
        __syncthreads();   // z(t) visible; zw WAR-safe (double buffer)

        if (chk && (tn & (TBLK - 1)) == 0 && tn < L) {
            unsigned int need = (unsigned)(tn >> 7);
            while (ldvol_(cntp + need) < 3u) { }
            __threadfence();
        }
        // prefetch gi(tn)
        float giN = __ldg(pG + offG), gnN = __ldg(pN + offG);

        float edn = ex2f_(gje * dtbuf[tn]);   // decay t -> t+1

        // dot over K-half: hand-pipelined depth-2 LDS, 96 fma2, 6 accs
        const ulonglong2* zc = (const ulonglong2*)(zr + (q ? 80 : 0));
        unsigned long long ar0 = 0, ar1 = 0, au0 = 0, au1 = 0, an0 = 0, an1 = 0;
        ulonglong2 v0 = zc[0];
        ulonglong2 v1 = zc[1];
        #pragma unroll
        for (int i = 0; i < 16; i += 2) {
            ulonglong2 n0, n1;
            if (i + 2 < 16) { n0 = zc[i + 2]; n1 = zc[i + 3]; }
            fma2(ar0, Wr[2*i],   v0.x); fma2(ar0, Wr[2*i+1], v0.y);
            fma2(au0, Wu[2*i],   v0.x); fma2(au0, Wu[2*i+1], v0.y);
            fma2(an0, Wn[2*i],   v0.x); fma2(an0, Wn[2*i+1], v0.y);
            fma2(ar1, Wr[2*i+2], v1.x); fma2(ar1, Wr[2*i+3], v1.y);
            fma2(au1, Wu[2*i+2], v1.x); fma2(au1, Wu[2*i+3], v1.y);
            fma2(an1, Wn[2*i+2], v1.x); fma2(an1, Wn[2*i+3], v1.y);
            v0 = n0; v1 = n1;
        }
        add2(ar0, ar1); add2(au0, au1); add2(an0, an1);
        float x, y;
        unpk(ar0, x, y); float Sr = x + y;   // pre-scaled by 0.5
        unpk(au0, x, y); float Su = x + y;
        unpk(an0, x, y); float Sn = x + y;

        if (q == 0) { Sr += gi_c; Sn += bh_n; }   // gi r-row prescaled 0.5
        else        { Su += gi_c; }

        Sr += __shfl_xor_sync(0xffffffffu, Sr, 1);
        Su += __shfl_xor_sync(0xffffffffu, Su, 1);
        Sn += __shfl_xor_sync(0xffffffffu, Sn, 1);

        // r: fast MUFU.TANH form; u: precise; n: fast MUFU.TANH
        float uu = sigmoidf_(Su);                     // off critical chain
        float rr = fmaf(tanhap_(Sr), 0.5f, 0.5f);
        float nn = tanhap_(fmaf(rr, Sn, gn_c));
        float znew = nn + uu * (zdj - nn);
        float zd   = znew * edn;
        if (q == 0) { zw[wj] = zd; *(zp + offZ) = znew; }
        zdj   = zd;
        zlast = znew;

        gi_c = giN; gn_c = gnN;
    };

    int t = 0;
    while (t + 2 <= L) {
        step(t + 1, 0,  0,   false, zbA, zbB);
        step(t + 2, GG, DZC, true,  zbB, zbA);
        pG += 2 * GG; pN += 2 * GG; zp += 2 * DZC;
        t += 2;
    }
    if (t < L) {   // leftover odd step; parity: read zbA
        step(t + 1, 0, 0, false, zbA, zbB);
        t += 1;
    }

    // closed-form inactive tail: z_out(k) = z_{L-1} * exp(-gamma*(ts[k]-ts[L-1]))
    {
        const float* tsrc = t_dyn + (size_t)b * TT;
        float tl = __ldg(tsrc + (L - 1));
        float zl = zlast;
        if (q == 0) {
            float tend = __ldg(tsrc + (TT - 1));
            z_final[(size_t)b * DZC + j] = zl * ex2f_(gje * (tend - tl));
        }
        float* zob = Z_traj + (size_t)b * TT * DZC + j;
        for (int k = L + q; k < TT; k += 2) {
            float v = zl * ex2f_(gje * (__ldg(tsrc + k) - tl));
            zob[(size_t)k * DZC] = v;
        }
    }
}

// =====================================================================
// launch
// =====================================================================
extern "C" void kernel_launch(void* const* d_in, const int* in_sizes, int n_in,
                              void* d_out, int out_size)
{
    const float* z0        = (const float*)d_in[0];
    const float* t_dyn     = (const float*)d_in[1];
    const float* Y         = (const float*)d_in[2];
    const float* M         = (const float*)d_in[3];
    const int*   dyn_lens  = (const int*)  d_in[4];
    const float* H         = (const float*)d_in[5];
    const float* W_ih      = (const float*)d_in[6];
    const float* b_ih      = (const float*)d_in[7];
    const float* W_hh      = (const float*)d_in[8];
    const float* b_hh      = (const float*)d_in[9];
    const float* log_gamma = (const float*)d_in[10];

    float* out     = (float*)d_out;
    float* z_final = out;                       // (B, DZ)
    float* Z_traj  = out + (size_t)BB * DZC;    // (B, T, DZ)

    void* cnt_ptr = nullptr;
    cudaGetSymbolAddress(&cnt_ptr, g_cnt);
    cudaMemsetAsync(cnt_ptr, 0, sizeof(unsigned int) * BB * NTBLK);

    fused_kernel<<<SCAN_CTAS + GEMM_CTAS, 256>>>(
        z0, t_dyn, dyn_lens, Y, M, H, W_ih, b_ih, W_hh, b_hh, log_gamma,
        z_final, Z_traj);
}

// round 11
// speedup vs baseline: 2.3343x; 1.0526x over previous
#include <cuda_runtime.h>
#include <cuda_bf16.h>
#include <math.h>

// Problem constants
#define BB   32
#define TT   4096
#define DZC  128
#define NDC  32
#define DHC  128
#define GG   384            // 3*DZ
#define IND  192            // 2*ND + DH

#define TBLK      128                 // timesteps per GEMM tile
#define NTBLK     (TT / TBLK)         // 32 t-blocks per batch
#define GEMM_CTAS (NTBLK * BB * 3)    // 3072
#define SCAN_CTAS BB                  // 32

// z exchange buffer: halves padded 16 floats apart -> bank-disjoint reads
#define ZPAD 144

// ---------------- scratch (no cudaMalloc allowed) ----------------
__device__ float        g_gi[(size_t)BB * TT * GG + 2 * GG];
__device__ unsigned int g_cnt[BB * NTBLK];

// ---------------- packed fp32x2 helpers (sm_100+) ----------------
__device__ __forceinline__ void fma2(unsigned long long& d,
                                     unsigned long long a,
                                     unsigned long long b) {
    asm("fma.rn.f32x2 %0, %1, %2, %0;" : "+l"(d) : "l"(a), "l"(b));
}
__device__ __forceinline__ void add2(unsigned long long& d, unsigned long long a) {
    asm("add.rn.f32x2 %0, %0, %1;" : "+l"(d) : "l"(a));
}
__device__ __forceinline__ unsigned long long dup2(float a) {
    unsigned long long r;
    asm("mov.b64 %0, {%1, %1};" : "=l"(r) : "f"(a));
    return r;
}
__device__ __forceinline__ unsigned long long pack2(float x, float y) {
    unsigned long long r;
    asm("mov.b64 %0, {%1, %2};" : "=l"(r) : "f"(x), "f"(y));
    return r;
}
__device__ __forceinline__ void unpk(unsigned long long v, float& x, float& y) {
    asm("mov.b64 {%0, %1}, %2;" : "=f"(x), "=f"(y) : "l"(v));
}
__device__ __forceinline__ float ex2f_(float x) {
    float y; asm("ex2.approx.f32 %0, %1;" : "=f"(y) : "f"(x)); return y;
}
__device__ __forceinline__ float tanhap_(float x) {
    float y; asm("tanh.approx.f32 %0, %1;" : "=f"(y) : "f"(x)); return y;
}
__device__ __forceinline__ unsigned int ldvol_(const unsigned int* p) {
    unsigned int v;
    asm volatile("ld.volatile.global.b32 %0, [%1];" : "=r"(v) : "l"(p));
    return v;
}

// =====================================================================
// Fused kernel. blockIdx.x < 32  -> scan role (one CTA per batch)
//               blockIdx.x >= 32 -> GEMM tile role (t-block-major order)
// GEMM adds b_ih; folds b_hh for r/u rows; r AND u rows prescaled 0.5
// to match gate = 0.5 + 0.5*tanh(0.5*x).
// =====================================================================
#define Bb 128
#define BN 128
#define BK 16

struct ScanSmem {
    float dtbuf[TT + 4];
    float zbA[ZPAD];
    float zbB[ZPAD];
};
struct GemmSmem {
    float As[2][BK][Bb];
    float Bs[2][BK][BN];
};

__global__ __launch_bounds__(256, 1) void fused_kernel(
    const float* __restrict__ z0, const float* __restrict__ t_dyn,
    const int* __restrict__ dyn_lens,
    const float* __restrict__ Y, const float* __restrict__ M,
    const float* __restrict__ H,
    const float* __restrict__ W_ih, const float* __restrict__ b_ih,
    const float* __restrict__ W_hh, const float* __restrict__ b_hh,
    const float* __restrict__ log_gamma,
    float* __restrict__ z_final, float* __restrict__ Z_traj)
{
    __shared__ __align__(16) union { ScanSmem scan; GemmSmem gemm; } sm;

    const int tid = threadIdx.x;

    if (blockIdx.x >= SCAN_CTAS) {
        // ================= GEMM role =================
        const int gidx = blockIdx.x - SCAN_CTAS;
        const int tb   = gidx / (BB * 3);
        const int rem  = gidx % (BB * 3);
        const int b    = rem / 3;
        const int gblk = rem % 3;
        const int bt0  = b * TT + tb * TBLK;
        const int g0   = gblk * BN;
        const float wscale = (gblk < 2) ? 0.5f : 1.0f;   // r,u-row prescale

        float* gi = g_gi;
        const int tx = tid & 15;
        const int ty = tid >> 4;

        unsigned long long acc[8][4];
        #pragma unroll
        for (int i = 0; i < 8; i++)
            #pragma unroll
            for (int j = 0; j < 4; j++) acc[i][j] = 0ull;

        auto loadA = [&](int stage, int kc) {
            #pragma unroll
            for (int i = 0; i < 2; i++) {
                int e  = tid + 256 * i;
                int m  = e & 127;
                int k4 = e >> 7;
                int kk = kc * BK + k4 * 4;
                int bt = bt0 + m;
                float4 v;
                if (kk < 32)       v = *(const float4*)(Y + (size_t)bt * NDC + kk);
                else if (kk < 64)  v = *(const float4*)(M + (size_t)bt * NDC + (kk - 32));
                else               v = *(const float4*)(H + (size_t)bt * DHC + (kk - 64));
                sm.gemm.As[stage][k4 * 4 + 0][m] = v.x;
                sm.gemm.As[stage][k4 * 4 + 1][m] = v.y;
                sm.gemm.As[stage][k4 * 4 + 2][m] = v.z;
                sm.gemm.As[stage][k4 * 4 + 3][m] = v.w;
            }
        };
        auto loadB = [&](int stage, int kc) {
            #pragma unroll
            for (int i = 0; i < 2; i++) {
                int e  = tid + 256 * i;
                int g  = e & 127;
                int k4 = e >> 7;
                int kk = kc * BK + k4 * 4;
                float4 v = *(const float4*)(W_ih + (size_t)(g0 + g) * IND + kk);
                sm.gemm.Bs[stage][k4 * 4 + 0][g] = v.x * wscale;
                sm.gemm.Bs[stage][k4 * 4 + 1][g] = v.y * wscale;
                sm.gemm.Bs[stage][k4 * 4 + 2][g] = v.z * wscale;
                sm.gemm.Bs[stage][k4 * 4 + 3][g] = v.w * wscale;
            }
        };

        loadA(0, 0); loadB(0, 0);
        __syncthreads();

        const int NKC = IND / BK;   // 12
        for (int kc = 0; kc < NKC; kc++) {
            int cur = kc & 1, nxt = cur ^ 1;
            if (kc + 1 < NKC) { loadA(nxt, kc + 1); loadB(nxt, kc + 1); }
            #pragma unroll
            for (int k = 0; k < BK; k++) {
                float a[8];
                *(float4*)&a[0] = *(const float4*)&sm.gemm.As[cur][k][ty * 8];
                *(float4*)&a[4] = *(const float4*)&sm.gemm.As[cur][k][ty * 8 + 4];
                unsigned long long bv[4];
                {
                    ulonglong2 b0 = *(const ulonglong2*)&sm.gemm.Bs[cur][k][tx * 8];
                    ulonglong2 b1 = *(const ulonglong2*)&sm.gemm.Bs[cur][k][tx * 8 + 4];
                    bv[0] = b0.x; bv[1] = b0.y; bv[2] = b1.x; bv[3] = b1.y;
                }
                #pragma unroll
                for (int i = 0; i < 8; i++) {
                    unsigned long long ad = dup2(a[i]);
                    fma2(acc[i][0], ad, bv[0]);
                    fma2(acc[i][1], ad, bv[1]);
                    fma2(acc[i][2], ad, bv[2]);
                    fma2(acc[i][3], ad, bv[3]);
                }
            }
            __syncthreads();
        }

        // bias: b_ih; fold b_hh for r/u rows; r,u rows scaled 0.5
        float bia[8];
        *(float4*)&bia[0] = *(const float4*)(b_ih + g0 + tx * 8);
        *(float4*)&bia[4] = *(const float4*)(b_ih + g0 + tx * 8 + 4);
        if (gblk < 2) {
            float bh[8];
            *(float4*)&bh[0] = *(const float4*)(b_hh + g0 + tx * 8);
            *(float4*)&bh[4] = *(const float4*)(b_hh + g0 + tx * 8 + 4);
            #pragma unroll
            for (int j = 0; j < 8; j++) bia[j] = (bia[j] + bh[j]) * 0.5f;
        }

        #pragma unroll
        for (int i = 0; i < 8; i++) {
            float c[8];
            unpk(acc[i][0], c[0], c[1]);
            unpk(acc[i][1], c[2], c[3]);
            unpk(acc[i][2], c[4], c[5]);
            unpk(acc[i][3], c[6], c[7]);
            #pragma unroll
            for (int j = 0; j < 8; j++) c[j] += bia[j];
            int bt = bt0 + ty * 8 + i;
            float* outp = gi + (size_t)bt * GG + g0 + tx * 8;
            *(float4*)(outp)     = *(float4*)&c[0];
            *(float4*)(outp + 4) = *(float4*)&c[4];
        }

        __threadfence();
        __syncthreads();
        if (tid == 0) atomicAdd(&g_cnt[b * NTBLK + tb], 1u);
        return;
    }

    // ================= scan role =================
    const int b = blockIdx.x;
    const int j = tid >> 1;     // state dim 0..127
    const int q = tid & 1;      // K-half 0..1

    float* dtbuf = sm.scan.dtbuf;
    float* zbA   = sm.scan.zbA;
    float* zbB   = sm.scan.zbB;

    // dt[t] = max(ts[t]-ts[t-1],0), dt[0]=0, dt[TT]=0
    {
        const float* tp = t_dyn + (size_t)b * TT;
        for (int i = tid; i < TT; i += 256) {
            float cur = __ldg(tp + i);
            float prv = (i > 0) ? __ldg(tp + i - 1) : cur;
            dtbuf[i] = fmaxf(cur - prv, 0.0f);
        }
        if (tid == 0) dtbuf[TT] = 0.0f;
    }

    // weights: rows {j, 128+j, 256+j}, K half [64q, 64q+64) -> 96 u64
    // Wr AND Wu prescaled by 0.5 (gate = 0.5 + 0.5*tanh(0.5*x))
    unsigned long long Wr[32], Wu[32], Wn[32];
    {
        const float4* wr = (const float4*)(W_hh + (size_t)j * DZC + 64 * q);
        const float4* wu = (const float4*)(W_hh + (size_t)(128 + j) * DZC + 64 * q);
        const float4* wn = (const float4*)(W_hh + (size_t)(256 + j) * DZC + 64 * q);
        #pragma unroll
        for (int i = 0; i < 16; i++) {
            float4 a = wr[i];
            Wr[2*i]   = pack2(a.x * 0.5f, a.y * 0.5f);
            Wr[2*i+1] = pack2(a.z * 0.5f, a.w * 0.5f);
            float4 c = wu[i];
            Wu[2*i]   = pack2(c.x * 0.5f, c.y * 0.5f);
            Wu[2*i+1] = pack2(c.z * 0.5f, c.w * 0.5f);
            float4 d = wn[i];
            Wn[2*i]   = pack2(d.x, d.y);
            Wn[2*i+1] = pack2(d.z, d.w);
        }
    }
    const float bh_n = (q == 0) ? b_hh[256 + j] : 0.0f;  // r/u bias folded in GEMM
    const int   L    = dyn_lens[b];                      // active steps (>=1)

    float lg  = log_gamma[j];
    float sp  = (lg > 20.0f) ? lg : log1pf(expf(lg));   // softplus
    const float gje = -1.4426950408889634f * sp;

    const unsigned int* cntp = &g_cnt[b * NTBLK];

    // padded z layout: dim k at index k + 16*(k>=64)
    const int wj = j + ((j >> 6) << 4);

    while (ldvol_(cntp) < 3u) { }
    __threadfence();

    // gi streams, distance-1 prefetch; pG/pN point at row t+1 at step t entry
    const float* pG = g_gi + (size_t)b * TT * GG + q * DZC + j;
    const float* pN = g_gi + (size_t)b * TT * GG + 2 * DZC + j;
    float gi_c = __ldg(pG);
    float gn_c = __ldg(pN);
    pG += GG; pN += GG;

    float* zp = Z_traj + (size_t)b * TT * DZC + j;   // row t at pair entry

    float zdj = z0[(size_t)b * DZC + j];
    float zlast = zdj;
    if (q == 0) zbA[wj] = zdj;

    // one active step; tn = t+1; offsets are call-site literals
    auto step = [&](int tn, int offG, int offZ, bool chk,
                    const float* __restrict__ zr, float* __restrict__ zw) {
        __syncthreads();   // z(t) visible; zw WAR-safe (double buffer)

        if (chk && (tn & (TBLK - 1)) == 0 && tn < L) {
            unsigned int need = (unsigned)(tn >> 7);
            while (ldvol_(cntp + need) < 3u) { }
            __threadfence();
        }
        // prefetch gi(tn)
        float giN = __ldg(pG + offG), gnN = __ldg(pN + offG);

        float edn = ex2f_(gje * dtbuf[tn]);   // decay t -> t+1

        // dot over K-half: hand-pipelined depth-2 LDS, 96 fma2, 6 accs
        const ulonglong2* zc = (const ulonglong2*)(zr + (q ? 80 : 0));
        unsigned long long ar0 = 0, ar1 = 0, au0 = 0, au1 = 0, an0 = 0, an1 = 0;
        ulonglong2 v0 = zc[0];
        ulonglong2 v1 = zc[1];
        #pragma unroll
        for (int i = 0; i < 16; i += 2) {
            ulonglong2 n0, n1;
            if (i + 2 < 16) { n0 = zc[i + 2]; n1 = zc[i + 3]; }
            fma2(ar0, Wr[2*i],   v0.x); fma2(ar0, Wr[2*i+1], v0.y);
            fma2(au0, Wu[2*i],   v0.x); fma2(au0, Wu[2*i+1], v0.y);
            fma2(an0, Wn[2*i],   v0.x); fma2(an0, Wn[2*i+1], v0.y);
            fma2(ar1, Wr[2*i+2], v1.x); fma2(ar1, Wr[2*i+3], v1.y);
            fma2(au1, Wu[2*i+2], v1.x); fma2(au1, Wu[2*i+3], v1.y);
            fma2(an1, Wn[2*i+2], v1.x); fma2(an1, Wn[2*i+3], v1.y);
            v0 = n0; v1 = n1;
        }
        add2(ar0, ar1); add2(au0, au1); add2(an0, an1);
        float x, y;
        unpk(ar0, x, y); float Sr = x + y;   // pre-scaled by 0.5
        unpk(au0, x, y); float Su = x + y;   // pre-scaled by 0.5
        unpk(an0, x, y); float Sn = x + y;

        if (q == 0) { Sr += gi_c; Sn += bh_n; }   // gi r-row prescaled 0.5
        else        { Su += gi_c; }               // gi u-row prescaled 0.5

        Sr += __shfl_xor_sync(0xffffffffu, Sr, 1);
        Su += __shfl_xor_sync(0xffffffffu, Su, 1);
        Sn += __shfl_xor_sync(0xffffffffu, Sn, 1);

        // all three gates via MUFU.TANH
        float rr = fmaf(tanhap_(Sr), 0.5f, 0.5f);
        float uu = fmaf(tanhap_(Su), 0.5f, 0.5f);
        float nn = tanhap_(fmaf(rr, Sn, gn_c));
        float znew = nn + uu * (zdj - nn);
        float zd   = znew * edn;
        if (q == 0) { zw[wj] = zd; *(zp + offZ) = znew; }
        zdj   = zd;
        zlast = znew;

        gi_c = giN; gn_c = gnN;
    };

    int t = 0;
    while (t + 2 <= L) {
        step(t + 1, 0,  0,   false, zbA, zbB);
        step(t + 2, GG, DZC, true,  zbB, zbA);
        pG += 2 * GG; pN += 2 * GG; zp += 2 * DZC;
        t += 2;
    }
    if (t < L) {   // leftover odd step; parity: read zbA
        step(t + 1, 0, 0, false, zbA, zbB);
        t += 1;
    }

    // closed-form inactive tail: z_out(k) = z_{L-1} * exp(-gamma*(ts[k]-ts[L-1]))
    {
        const float* tsrc = t_dyn + (size_t)b * TT;
        float tl = __ldg(tsrc + (L - 1));
        float zl = zlast;
        if (q == 0) {
            float tend = __ldg(tsrc + (TT - 1));
            z_final[(size_t)b * DZC + j] = zl * ex2f_(gje * (tend - tl));
        }
        float* zob = Z_traj + (size_t)b * TT * DZC + j;
        for (int k = L + q; k < TT; k += 2) {
            float v = zl * ex2f_(gje * (__ldg(tsrc + k) - tl));
            zob[(size_t)k * DZC] = v;
        }
    }
}

// =====================================================================
// launch
// =====================================================================
extern "C" void kernel_launch(void* const* d_in, const int* in_sizes, int n_in,
                              void* d_out, int out_size)
{
    const float* z0        = (const float*)d_in[0];
    const float* t_dyn     = (const float*)d_in[1];
    const float* Y         = (const float*)d_in[2];
    const float* M         = (const float*)d_in[3];
    const int*   dyn_lens  = (const int*)  d_in[4];
    const float* H         = (const float*)d_in[5];
    const float* W_ih      = (const float*)d_in[6];
    const float* b_ih      = (const float*)d_in[7];
    const float* W_hh      = (const float*)d_in[8];
    const float* b_hh      = (const float*)d_in[9];
    const float* log_gamma = (const float*)d_in[10];

    float* out     = (float*)d_out;
    float* z_final = out;                       // (B, DZ)
    float* Z_traj  = out + (size_t)BB * DZC;    // (B, T, DZ)

    void* cnt_ptr = nullptr;
    cudaGetSymbolAddress(&cnt_ptr, g_cnt);
    cudaMemsetAsync(cnt_ptr, 0, sizeof(unsigned int) * BB * NTBLK);

    fused_kernel<<<SCAN_CTAS + GEMM_CTAS, 256>>>(
        z0, t_dyn, dyn_lens, Y, M, H, W_ih, b_ih, W_hh, b_hh, log_gamma,
        z_final, Z_traj);
}

// round 12
// speedup vs baseline: 2.3397x; 1.0023x over previous
#include <cuda_runtime.h>
#include <cuda_bf16.h>
#include <math.h>

// Problem constants
#define BB   32
#define TT   4096
#define DZC  128
#define NDC  32
#define DHC  128
#define GG   384            // 3*DZ
#define IND  192            // 2*ND + DH

#define TBLK      128                 // timesteps per GEMM tile
#define NTBLK     (TT / TBLK)         // 32 t-blocks per batch
#define GEMM_CTAS (NTBLK * BB * 3)    // 3072
#define SCAN_CTAS BB                  // 32

// z exchange buffer: halves padded 16 floats apart -> bank-disjoint reads
#define ZPAD 144

// ---------------- scratch (no cudaMalloc allowed) ----------------
__device__ float        g_gi[(size_t)BB * TT * GG + 2 * GG];
__device__ unsigned int g_cnt[BB * NTBLK];

// ---------------- packed fp32x2 helpers (sm_100+) ----------------
__device__ __forceinline__ void fma2(unsigned long long& d,
                                     unsigned long long a,
                                     unsigned long long b) {
    asm("fma.rn.f32x2 %0, %1, %2, %0;" : "+l"(d) : "l"(a), "l"(b));
}
__device__ __forceinline__ void add2(unsigned long long& d, unsigned long long a) {
    asm("add.rn.f32x2 %0, %0, %1;" : "+l"(d) : "l"(a));
}
__device__ __forceinline__ unsigned long long dup2(float a) {
    unsigned long long r;
    asm("mov.b64 %0, {%1, %1};" : "=l"(r) : "f"(a));
    return r;
}
__device__ __forceinline__ unsigned long long pack2(float x, float y) {
    unsigned long long r;
    asm("mov.b64 %0, {%1, %2};" : "=l"(r) : "f"(x), "f"(y));
    return r;
}
__device__ __forceinline__ void unpk(unsigned long long v, float& x, float& y) {
    asm("mov.b64 {%0, %1}, %2;" : "=f"(x), "=f"(y) : "l"(v));
}
__device__ __forceinline__ float ex2f_(float x) {
    float y; asm("ex2.approx.f32 %0, %1;" : "=f"(y) : "f"(x)); return y;
}
__device__ __forceinline__ float tanhap_(float x) {
    float y; asm("tanh.approx.f32 %0, %1;" : "=f"(y) : "f"(x)); return y;
}
__device__ __forceinline__ unsigned int ldvol_(const unsigned int* p) {
    unsigned int v;
    asm volatile("ld.volatile.global.b32 %0, [%1];" : "=r"(v) : "l"(p));
    return v;
}

// =====================================================================
// Fused kernel. blockIdx.x < 32  -> scan role (one CTA per batch)
//               blockIdx.x >= 32 -> GEMM tile role (t-block-major order)
// GEMM adds b_ih; folds b_hh for r/u rows; r AND u rows prescaled 0.5
// to match gate = 0.5 + 0.5*tanh(0.5*x).
// =====================================================================
#define Bb 128
#define BN 128
#define BK 16

struct ScanSmem {
    float dtbuf[TT + 4];
    float zbA[ZPAD];
    float zbB[ZPAD];
};
struct GemmSmem {
    float As[2][BK][Bb];
    float Bs[2][BK][BN];
};

__global__ __launch_bounds__(256, 1) void fused_kernel(
    const float* __restrict__ z0, const float* __restrict__ t_dyn,
    const int* __restrict__ dyn_lens,
    const float* __restrict__ Y, const float* __restrict__ M,
    const float* __restrict__ H,
    const float* __restrict__ W_ih, const float* __restrict__ b_ih,
    const float* __restrict__ W_hh, const float* __restrict__ b_hh,
    const float* __restrict__ log_gamma,
    float* __restrict__ z_final, float* __restrict__ Z_traj)
{
    __shared__ __align__(16) union { ScanSmem scan; GemmSmem gemm; } sm;

    const int tid = threadIdx.x;

    if (blockIdx.x >= SCAN_CTAS) {
        // ================= GEMM role =================
        const int gidx = blockIdx.x - SCAN_CTAS;
        const int tb   = gidx / (BB * 3);
        const int rem  = gidx % (BB * 3);
        const int b    = rem / 3;
        const int gblk = rem % 3;
        const int bt0  = b * TT + tb * TBLK;
        const int g0   = gblk * BN;
        const float wscale = (gblk < 2) ? 0.5f : 1.0f;   // r,u-row prescale

        float* gi = g_gi;
        const int tx = tid & 15;
        const int ty = tid >> 4;

        unsigned long long acc[8][4];
        #pragma unroll
        for (int i = 0; i < 8; i++)
            #pragma unroll
            for (int j = 0; j < 4; j++) acc[i][j] = 0ull;

        auto loadA = [&](int stage, int kc) {
            #pragma unroll
            for (int i = 0; i < 2; i++) {
                int e  = tid + 256 * i;
                int m  = e & 127;
                int k4 = e >> 7;
                int kk = kc * BK + k4 * 4;
                int bt = bt0 + m;
                float4 v;
                if (kk < 32)       v = *(const float4*)(Y + (size_t)bt * NDC + kk);
                else if (kk < 64)  v = *(const float4*)(M + (size_t)bt * NDC + (kk - 32));
                else               v = *(const float4*)(H + (size_t)bt * DHC + (kk - 64));
                sm.gemm.As[stage][k4 * 4 + 0][m] = v.x;
                sm.gemm.As[stage][k4 * 4 + 1][m] = v.y;
                sm.gemm.As[stage][k4 * 4 + 2][m] = v.z;
                sm.gemm.As[stage][k4 * 4 + 3][m] = v.w;
            }
        };
        auto loadB = [&](int stage, int kc) {
            #pragma unroll
            for (int i = 0; i < 2; i++) {
                int e  = tid + 256 * i;
                int g  = e & 127;
                int k4 = e >> 7;
                int kk = kc * BK + k4 * 4;
                float4 v = *(const float4*)(W_ih + (size_t)(g0 + g) * IND + kk);
                sm.gemm.Bs[stage][k4 * 4 + 0][g] = v.x * wscale;
                sm.gemm.Bs[stage][k4 * 4 + 1][g] = v.y * wscale;
                sm.gemm.Bs[stage][k4 * 4 + 2][g] = v.z * wscale;
                sm.gemm.Bs[stage][k4 * 4 + 3][g] = v.w * wscale;
            }
        };

        loadA(0, 0); loadB(0, 0);
        __syncthreads();

        const int NKC = IND / BK;   // 12
        for (int kc = 0; kc < NKC; kc++) {
            int cur = kc & 1, nxt = cur ^ 1;
            if (kc + 1 < NKC) { loadA(nxt, kc + 1); loadB(nxt, kc + 1); }
            #pragma unroll
            for (int k = 0; k < BK; k++) {
                float a[8];
                *(float4*)&a[0] = *(const float4*)&sm.gemm.As[cur][k][ty * 8];
                *(float4*)&a[4] = *(const float4*)&sm.gemm.As[cur][k][ty * 8 + 4];
                unsigned long long bv[4];
                {
                    ulonglong2 b0 = *(const ulonglong2*)&sm.gemm.Bs[cur][k][tx * 8];
                    ulonglong2 b1 = *(const ulonglong2*)&sm.gemm.Bs[cur][k][tx * 8 + 4];
                    bv[0] = b0.x; bv[1] = b0.y; bv[2] = b1.x; bv[3] = b1.y;
                }
                #pragma unroll
                for (int i = 0; i < 8; i++) {
                    unsigned long long ad = dup2(a[i]);
                    fma2(acc[i][0], ad, bv[0]);
                    fma2(acc[i][1], ad, bv[1]);
                    fma2(acc[i][2], ad, bv[2]);
                    fma2(acc[i][3], ad, bv[3]);
                }
            }
            __syncthreads();
        }

        // bias: b_ih; fold b_hh for r/u rows; r,u rows scaled 0.5
        float bia[8];
        *(float4*)&bia[0] = *(const float4*)(b_ih + g0 + tx * 8);
        *(float4*)&bia[4] = *(const float4*)(b_ih + g0 + tx * 8 + 4);
        if (gblk < 2) {
            float bh[8];
            *(float4*)&bh[0] = *(const float4*)(b_hh + g0 + tx * 8);
            *(float4*)&bh[4] = *(const float4*)(b_hh + g0 + tx * 8 + 4);
            #pragma unroll
            for (int j = 0; j < 8; j++) bia[j] = (bia[j] + bh[j]) * 0.5f;
        }

        #pragma unroll
        for (int i = 0; i < 8; i++) {
            float c[8];
            unpk(acc[i][0], c[0], c[1]);
            unpk(acc[i][1], c[2], c[3]);
            unpk(acc[i][2], c[4], c[5]);
            unpk(acc[i][3], c[6], c[7]);
            #pragma unroll
            for (int j = 0; j < 8; j++) c[j] += bia[j];
            int bt = bt0 + ty * 8 + i;
            float* outp = gi + (size_t)bt * GG + g0 + tx * 8;
            *(float4*)(outp)     = *(float4*)&c[0];
            *(float4*)(outp + 4) = *(float4*)&c[4];
        }

        __threadfence();
        __syncthreads();
        if (tid == 0) atomicAdd(&g_cnt[b * NTBLK + tb], 1u);
        return;
    }

    // ================= scan role =================
    const int b = blockIdx.x;
    const int j = tid >> 1;     // state dim 0..127
    const int q = tid & 1;      // K-half 0..1

    float* dtbuf = sm.scan.dtbuf;
    float* zbA   = sm.scan.zbA;
    float* zbB   = sm.scan.zbB;

    // dt[t] = max(ts[t]-ts[t-1],0), dt[0]=0, dt[TT]=0
    {
        const float* tp = t_dyn + (size_t)b * TT;
        for (int i = tid; i < TT; i += 256) {
            float cur = __ldg(tp + i);
            float prv = (i > 0) ? __ldg(tp + i - 1) : cur;
            dtbuf[i] = fmaxf(cur - prv, 0.0f);
        }
        if (tid == 0) dtbuf[TT] = 0.0f;
    }

    // weights: rows {j, 128+j, 256+j}, K half [64q, 64q+64) -> 96 u64
    // Wr AND Wu prescaled by 0.5 (gate = 0.5 + 0.5*tanh(0.5*x))
    unsigned long long Wr[32], Wu[32], Wn[32];
    {
        const float4* wr = (const float4*)(W_hh + (size_t)j * DZC + 64 * q);
        const float4* wu = (const float4*)(W_hh + (size_t)(128 + j) * DZC + 64 * q);
        const float4* wn = (const float4*)(W_hh + (size_t)(256 + j) * DZC + 64 * q);
        #pragma unroll
        for (int i = 0; i < 16; i++) {
            float4 a = wr[i];
            Wr[2*i]   = pack2(a.x * 0.5f, a.y * 0.5f);
            Wr[2*i+1] = pack2(a.z * 0.5f, a.w * 0.5f);
            float4 c = wu[i];
            Wu[2*i]   = pack2(c.x * 0.5f, c.y * 0.5f);
            Wu[2*i+1] = pack2(c.z * 0.5f, c.w * 0.5f);
            float4 d = wn[i];
            Wn[2*i]   = pack2(d.x, d.y);
            Wn[2*i+1] = pack2(d.z, d.w);
        }
    }
    const float bh_n = (q == 0) ? b_hh[256 + j] : 0.0f;  // r/u bias folded in GEMM
    const int   L    = dyn_lens[b];                      // active steps (>=1)

    float lg  = log_gamma[j];
    float sp  = (lg > 20.0f) ? lg : log1pf(expf(lg));   // softplus
    const float gje = -1.4426950408889634f * sp;

    const unsigned int* cntp = &g_cnt[b * NTBLK];

    // padded z layout: dim k at index k + 16*(k>=64)
    const int wj = j + ((j >> 6) << 4);

    while (ldvol_(cntp) < 3u) { }
    __threadfence();

    // gi streams, distance-1 prefetch; pG/pN point at row t+1 at step t entry
    const float* pG = g_gi + (size_t)b * TT * GG + q * DZC + j;
    const float* pN = g_gi + (size_t)b * TT * GG + 2 * DZC + j;
    float gi_c = __ldg(pG);
    float gn_c = __ldg(pN);
    pG += GG; pN += GG;

    float* zp = Z_traj + (size_t)b * TT * DZC + j;   // row t at pair entry

    float zdj = z0[(size_t)b * DZC + j];
    float zlast = zdj;
    if (q == 0) zbA[wj] = zdj;

    // one active step; tn = t+1; offsets are call-site literals
    auto step = [&](int tn, int offG, int offZ, bool chk,
                    const float* __restrict__ zr, float* __restrict__ zw) {
        __syncthreads();   // z(t) visible; zw WAR-safe (double buffer)

        if (chk && (tn & (TBLK - 1)) == 0 && tn < L) {
            unsigned int need = (unsigned)(tn >> 7);
            while (ldvol_(cntp + need) < 3u) { }
            __threadfence();
        }
        // prefetch gi(tn)
        float giN = __ldg(pG + offG), gnN = __ldg(pN + offG);

        float edn = ex2f_(gje * dtbuf[tn]);   // decay t -> t+1

        const ulonglong2* zc = (const ulonglong2*)(zr + (q ? 80 : 0));

        // ---- pass 1: r,u dots (64 fma2); finish early so shfl+MUFU
        //      latency hides under pass-2 fma issue ----
        unsigned long long ar0 = 0, ar1 = 0, au0 = 0, au1 = 0;
        {
            ulonglong2 v0 = zc[0];
            ulonglong2 v1 = zc[1];
            #pragma unroll
            for (int i = 0; i < 16; i += 2) {
                ulonglong2 n0, n1;
                if (i + 2 < 16) { n0 = zc[i + 2]; n1 = zc[i + 3]; }
                fma2(ar0, Wr[2*i],   v0.x); fma2(ar0, Wr[2*i+1], v0.y);
                fma2(au0, Wu[2*i],   v0.x); fma2(au0, Wu[2*i+1], v0.y);
                fma2(ar1, Wr[2*i+2], v1.x); fma2(ar1, Wr[2*i+3], v1.y);
                fma2(au1, Wu[2*i+2], v1.x); fma2(au1, Wu[2*i+3], v1.y);
                v0 = n0; v1 = n1;
            }
        }
        add2(ar0, ar1); add2(au0, au1);
        float x, y;
        unpk(ar0, x, y); float Sr = x + y;   // pre-scaled by 0.5
        unpk(au0, x, y); float Su = x + y;   // pre-scaled by 0.5
        if (q == 0) Sr += gi_c;              // gi r-row prescaled 0.5
        else        Su += gi_c;              // gi u-row prescaled 0.5
        Sr += __shfl_xor_sync(0xffffffffu, Sr, 1);
        Su += __shfl_xor_sync(0xffffffffu, Su, 1);
        float rr = fmaf(tanhap_(Sr), 0.5f, 0.5f);
        float uu = fmaf(tanhap_(Su), 0.5f, 0.5f);

        // ---- pass 2: n dot (32 fma2, z re-read: broadcast LDS) ----
        unsigned long long an0 = 0, an1 = 0;
        {
            ulonglong2 v0 = zc[0];
            ulonglong2 v1 = zc[1];
            #pragma unroll
            for (int i = 0; i < 16; i += 2) {
                ulonglong2 n0, n1;
                if (i + 2 < 16) { n0 = zc[i + 2]; n1 = zc[i + 3]; }
                fma2(an0, Wn[2*i],   v0.x); fma2(an0, Wn[2*i+1], v0.y);
                fma2(an1, Wn[2*i+2], v1.x); fma2(an1, Wn[2*i+3], v1.y);
                v0 = n0; v1 = n1;
            }
        }
        add2(an0, an1);
        unpk(an0, x, y); float Sn = x + y;
        if (q == 0) Sn += bh_n;
        Sn += __shfl_xor_sync(0xffffffffu, Sn, 1);

        // short tail: n-path only (rr, uu already resolved)
        float nn = tanhap_(fmaf(rr, Sn, gn_c));
        float znew = nn + uu * (zdj - nn);
        float zd   = znew * edn;
        if (q == 0) { zw[wj] = zd; *(zp + offZ) = znew; }
        zdj   = zd;
        zlast = znew;

        gi_c = giN; gn_c = gnN;
    };

    int t = 0;
    while (t + 2 <= L) {
        step(t + 1, 0,  0,   false, zbA, zbB);
        step(t + 2, GG, DZC, true,  zbB, zbA);
        pG += 2 * GG; pN += 2 * GG; zp += 2 * DZC;
        t += 2;
    }
    if (t < L) {   // leftover odd step; parity: read zbA
        step(t + 1, 0, 0, false, zbA, zbB);
        t += 1;
    }

    // closed-form inactive tail: z_out(k) = z_{L-1} * exp(-gamma*(ts[k]-ts[L-1]))
    {
        const float* tsrc = t_dyn + (size_t)b * TT;
        float tl = __ldg(tsrc + (L - 1));
        float zl = zlast;
        if (q == 0) {
            float tend = __ldg(tsrc + (TT - 1));
            z_final[(size_t)b * DZC + j] = zl * ex2f_(gje * (tend - tl));
        }
        float* zob = Z_traj + (size_t)b * TT * DZC + j;
        for (int k = L + q; k < TT; k += 2) {
            float v = zl * ex2f_(gje * (__ldg(tsrc + k) - tl));
            zob[(size_t)k * DZC] = v;
        }
    }
}

// =====================================================================
// launch
// =====================================================================
extern "C" void kernel_launch(void* const* d_in, const int* in_sizes, int n_in,
                              void* d_out, int out_size)
{
    const float* z0        = (const float*)d_in[0];
    const float* t_dyn     = (const float*)d_in[1];
    const float* Y         = (const float*)d_in[2];
    const float* M         = (const float*)d_in[3];
    const int*   dyn_lens  = (const int*)  d_in[4];
    const float* H         = (const float*)d_in[5];
    const float* W_ih      = (const float*)d_in[6];
    const float* b_ih      = (const float*)d_in[7];
    const float* W_hh      = (const float*)d_in[8];
    const float* b_hh      = (const float*)d_in[9];
    const float* log_gamma = (const float*)d_in[10];

    float* out     = (float*)d_out;
    float* z_final = out;                       // (B, DZ)
    float* Z_traj  = out + (size_t)BB * DZC;    // (B, T, DZ)

    void* cnt_ptr = nullptr;
    cudaGetSymbolAddress(&cnt_ptr, g_cnt);
    cudaMemsetAsync(cnt_ptr, 0, sizeof(unsigned int) * BB * NTBLK);

    fused_kernel<<<SCAN_CTAS + GEMM_CTAS, 256>>>(
        z0, t_dyn, dyn_lens, Y, M, H, W_ih, b_ih, W_hh, b_hh, log_gamma,
        z_final, Z_traj);
}